// round 1
// baseline (speedup 1.0000x reference)
#include <cuda_runtime.h>
#include <math.h>

#define TT    1024
#define BB    4
#define HH    16
#define DKK   64
#define DM    1024
#define BH    (BB*HH)      // 64
#define NROWS (BB*TT)      // 4096
#define NREL  65

// ---------------- scratch (device globals; no allocation allowed) ----------
__device__ float g_qW[BH * TT * DKK];            // 16 MB
__device__ float g_kW[BH * TT * DKK];            // 16 MB
__device__ float g_vW[BH * TT * DKK];            // 16 MB
__device__ float g_scores[(size_t)BH * TT * TT]; // 256 MB
__device__ float g_R[BH * TT * NREL];            // 17 MB
__device__ float g_Pr[BH * TT * NREL];           // 17 MB
__device__ float g_heads[NROWS * DM];            // 16 MB

// ---------------------------------------------------------------------------
// Projection GEMM: Out[(b,h),t,d] = sum_m X[b*T+t, m] * W[h, m, d]
// X: (4096, 1024) row-major. W: (H, DM, DK). Out: (BH, T, DK).
// 128x128x8 tiles, 256 threads, 8x8 micro-tile.
// ---------------------------------------------------------------------------
__global__ __launch_bounds__(256) void proj_gemm(const float* __restrict__ X,
                                                 const float* __restrict__ W,
                                                 float* __restrict__ Out)
{
    __shared__ float As[8][128];
    __shared__ float Bs[8][128];

    const int bm = blockIdx.y * 128;
    const int bn = blockIdx.x * 128;
    const int tid = threadIdx.x;
    const int ty = tid >> 4, tx = tid & 15;

    float acc[8][8];
#pragma unroll
    for (int i = 0; i < 8; i++)
#pragma unroll
        for (int j = 0; j < 8; j++) acc[i][j] = 0.f;

    const int rowA = tid >> 1;
    const int c4A  = (tid & 1) * 4;
    const int kB   = tid >> 5;
    const int n4B  = (tid & 31) * 4;
    const int hB   = (bn + n4B) >> 6;
    const int dB   = (bn + n4B) & 63;

    for (int k0 = 0; k0 < DM; k0 += 8) {
        float4 a = *(const float4*)&X[(size_t)(bm + rowA) * DM + k0 + c4A];
        As[c4A + 0][rowA] = a.x;
        As[c4A + 1][rowA] = a.y;
        As[c4A + 2][rowA] = a.z;
        As[c4A + 3][rowA] = a.w;
        float4 b = *(const float4*)&W[((size_t)hB * DM + (k0 + kB)) * DKK + dB];
        *(float4*)&Bs[kB][n4B] = b;
        __syncthreads();
#pragma unroll
        for (int kk = 0; kk < 8; kk++) {
            float ra[8], rb[8];
#pragma unroll
            for (int i = 0; i < 8; i++) ra[i] = As[kk][ty * 8 + i];
#pragma unroll
            for (int j = 0; j < 8; j++) rb[j] = Bs[kk][tx * 8 + j];
#pragma unroll
            for (int i = 0; i < 8; i++)
#pragma unroll
                for (int j = 0; j < 8; j++) acc[i][j] += ra[i] * rb[j];
        }
        __syncthreads();
    }

#pragma unroll
    for (int i = 0; i < 8; i++) {
        int row = bm + ty * 8 + i;
        int b = row >> 10, t = row & 1023;
#pragma unroll
        for (int j = 0; j < 8; j++) {
            int col = bn + tx * 8 + j;
            int h = col >> 6, d = col & 63;
            Out[((size_t)(b * HH + h) * TT + t) * DKK + d] = acc[i][j];
        }
    }
}

// ---------------------------------------------------------------------------
// Output GEMM: C[n, m] = sum_k A[n, k] * Bm[k, m]. All row-major 1024-wide.
// ---------------------------------------------------------------------------
__global__ __launch_bounds__(256) void out_gemm(const float* __restrict__ A,
                                                const float* __restrict__ Bm,
                                                float* __restrict__ C)
{
    __shared__ float As[8][128];
    __shared__ float Bs[8][128];

    const int bm = blockIdx.y * 128;
    const int bn = blockIdx.x * 128;
    const int tid = threadIdx.x;
    const int ty = tid >> 4, tx = tid & 15;

    float acc[8][8];
#pragma unroll
    for (int i = 0; i < 8; i++)
#pragma unroll
        for (int j = 0; j < 8; j++) acc[i][j] = 0.f;

    const int rowA = tid >> 1;
    const int c4A  = (tid & 1) * 4;
    const int kB   = tid >> 5;
    const int n4B  = (tid & 31) * 4;

    for (int k0 = 0; k0 < DM; k0 += 8) {
        float4 a = *(const float4*)&A[(size_t)(bm + rowA) * DM + k0 + c4A];
        As[c4A + 0][rowA] = a.x;
        As[c4A + 1][rowA] = a.y;
        As[c4A + 2][rowA] = a.z;
        As[c4A + 3][rowA] = a.w;
        float4 b = *(const float4*)&Bm[(size_t)(k0 + kB) * DM + bn + n4B];
        *(float4*)&Bs[kB][n4B] = b;
        __syncthreads();
#pragma unroll
        for (int kk = 0; kk < 8; kk++) {
            float ra[8], rb[8];
#pragma unroll
            for (int i = 0; i < 8; i++) ra[i] = As[kk][ty * 8 + i];
#pragma unroll
            for (int j = 0; j < 8; j++) rb[j] = Bs[kk][tx * 8 + j];
#pragma unroll
            for (int i = 0; i < 8; i++)
#pragma unroll
                for (int j = 0; j < 8; j++) acc[i][j] += ra[i] * rb[j];
        }
        __syncthreads();
    }

#pragma unroll
    for (int i = 0; i < 8; i++) {
        int row = bm + ty * 8 + i;
        float4 v0 = make_float4(acc[i][0], acc[i][1], acc[i][2], acc[i][3]);
        float4 v1 = make_float4(acc[i][4], acc[i][5], acc[i][6], acc[i][7]);
        *(float4*)&C[(size_t)row * DM + bn + tx * 8]     = v0;
        *(float4*)&C[(size_t)row * DM + bn + tx * 8 + 4] = v1;
    }
}

// ---------------------------------------------------------------------------
// R[bh, t, r] = sum_k qW[bh, t, k] * emb_Q[r, k].  One warp per row.
// ---------------------------------------------------------------------------
__global__ __launch_bounds__(256) void r_gemm(const float* __restrict__ Q,
                                              const float* __restrict__ embQ,
                                              float* __restrict__ R)
{
    __shared__ float sE[NREL][DKK + 1]; // +1 pad: conflict-free column reads
    __shared__ float sQ[8][DKK];
    const int tid = threadIdx.x;
    for (int i = tid; i < NREL * DKK; i += 256) sE[i >> 6][i & 63] = embQ[i];
    const int warp = tid >> 5, lane = tid & 31;
    const size_t row = (size_t)blockIdx.x * 8 + warp;
    sQ[warp][lane]      = Q[row * DKK + lane];
    sQ[warp][lane + 32] = Q[row * DKK + lane + 32];
    __syncthreads();
    float a0 = 0.f, a1 = 0.f, a2 = 0.f;
#pragma unroll
    for (int k = 0; k < DKK; k++) {
        float q = sQ[warp][k];
        a0 += q * sE[lane][k];
        a1 += q * sE[lane + 32][k];
        a2 += q * sE[64][k];
    }
    R[row * NREL + lane]      = a0;
    R[row * NREL + lane + 32] = a1;
    if (lane == 0) R[row * NREL + 64] = a2;
}

// ---------------------------------------------------------------------------
// Scores: S[bh, t, s] = (qW[t,:]·kW[s,:] + R[bh,t,rel(t,s)]) / 8
// NT GEMM per batch, 128x128 tiles, K=64.
// ---------------------------------------------------------------------------
__global__ __launch_bounds__(256) void scores_gemm(const float* __restrict__ Q,
                                                   const float* __restrict__ Kw,
                                                   const float* __restrict__ R,
                                                   float* __restrict__ S)
{
    const int bh = blockIdx.z;
    const float* Aq = Q  + (size_t)bh * TT * DKK;
    const float* Bk = Kw + (size_t)bh * TT * DKK;
    float*       Sc = S  + (size_t)bh * TT * TT;
    const float* Rb = R  + (size_t)bh * TT * NREL;

    const int bm = blockIdx.y * 128;
    const int bn = blockIdx.x * 128;
    const int tid = threadIdx.x;
    const int ty = tid >> 4, tx = tid & 15;

    __shared__ float As[8][128];
    __shared__ float Bs[8][128];

    float acc[8][8];
#pragma unroll
    for (int i = 0; i < 8; i++)
#pragma unroll
        for (int j = 0; j < 8; j++) acc[i][j] = 0.f;

    const int rowL = tid >> 1;
    const int c4L  = (tid & 1) * 4;

    for (int k0 = 0; k0 < DKK; k0 += 8) {
        float4 a = *(const float4*)&Aq[(size_t)(bm + rowL) * DKK + k0 + c4L];
        As[c4L + 0][rowL] = a.x;
        As[c4L + 1][rowL] = a.y;
        As[c4L + 2][rowL] = a.z;
        As[c4L + 3][rowL] = a.w;
        float4 b = *(const float4*)&Bk[(size_t)(bn + rowL) * DKK + k0 + c4L];
        Bs[c4L + 0][rowL] = b.x;
        Bs[c4L + 1][rowL] = b.y;
        Bs[c4L + 2][rowL] = b.z;
        Bs[c4L + 3][rowL] = b.w;
        __syncthreads();
#pragma unroll
        for (int kk = 0; kk < 8; kk++) {
            float ra[8], rb[8];
#pragma unroll
            for (int i = 0; i < 8; i++) ra[i] = As[kk][ty * 8 + i];
#pragma unroll
            for (int j = 0; j < 8; j++) rb[j] = Bs[kk][tx * 8 + j];
#pragma unroll
            for (int i = 0; i < 8; i++)
#pragma unroll
                for (int j = 0; j < 8; j++) acc[i][j] += ra[i] * rb[j];
        }
        __syncthreads();
    }

#pragma unroll
    for (int i = 0; i < 8; i++) {
        int t = bm + ty * 8 + i;
#pragma unroll
        for (int j = 0; j < 8; j++) {
            int s = bn + tx * 8 + j;
            int rr = s - t;
            rr = min(max(rr, -32), 32) + 32;
            Sc[(size_t)t * TT + s] = (acc[i][j] + Rb[t * NREL + rr]) * 0.125f;
        }
    }
}

// ---------------------------------------------------------------------------
// Row softmax (in place) + bucketed probability sums Pr[row, 0..64].
// One 256-thread block per row of length 1024.
// ---------------------------------------------------------------------------
__global__ __launch_bounds__(256) void softmax_kernel(float* __restrict__ S,
                                                      float* __restrict__ Pr)
{
    const size_t row = blockIdx.x;
    const int t = (int)(row & (TT - 1));
    float* Sr = S + row * (size_t)TT;

    __shared__ float sp[TT];
    __shared__ float red[8];
    __shared__ float redlo[8], redhi[8];

    const int tid = threadIdx.x;
    const int lane = tid & 31, warp = tid >> 5;

    float x0 = Sr[tid], x1 = Sr[tid + 256], x2 = Sr[tid + 512], x3 = Sr[tid + 768];
    float mx = fmaxf(fmaxf(x0, x1), fmaxf(x2, x3));
#pragma unroll
    for (int o = 16; o; o >>= 1) mx = fmaxf(mx, __shfl_xor_sync(0xffffffffu, mx, o));
    if (lane == 0) red[warp] = mx;
    __syncthreads();
    mx = red[0];
#pragma unroll
    for (int i = 1; i < 8; i++) mx = fmaxf(mx, red[i]);

    x0 = __expf(x0 - mx); x1 = __expf(x1 - mx);
    x2 = __expf(x2 - mx); x3 = __expf(x3 - mx);
    float sm = x0 + x1 + x2 + x3;
#pragma unroll
    for (int o = 16; o; o >>= 1) sm += __shfl_xor_sync(0xffffffffu, sm, o);
    __syncthreads();                 // everyone done reading red[] (max)
    if (lane == 0) red[warp] = sm;
    __syncthreads();
    sm = red[0] + red[1] + red[2] + red[3] + red[4] + red[5] + red[6] + red[7];
    float inv = 1.f / sm;
    x0 *= inv; x1 *= inv; x2 *= inv; x3 *= inv;

    sp[tid] = x0; sp[tid + 256] = x1; sp[tid + 512] = x2; sp[tid + 768] = x3;
    Sr[tid] = x0; Sr[tid + 256] = x1; Sr[tid + 512] = x2; Sr[tid + 768] = x3;
    __syncthreads();

    float* Prow = Pr + row * NREL;
    if (tid >= 1 && tid <= 63) {           // middle buckets: unique s each
        int s = t + tid - 32;
        Prow[tid] = (s >= 0 && s < TT) ? sp[s] : 0.f;
    }
    float lo = 0.f, hi = 0.f;              // clipped buckets r=0 / r=64
#pragma unroll
    for (int j = 0; j < 4; j++) {
        int s = tid + 256 * j;
        float p = sp[s];
        if (s <= t - 32) lo += p;
        if (s >= t + 32) hi += p;
    }
#pragma unroll
    for (int o = 16; o; o >>= 1) {
        lo += __shfl_xor_sync(0xffffffffu, lo, o);
        hi += __shfl_xor_sync(0xffffffffu, hi, o);
    }
    if (lane == 0) { redlo[warp] = lo; redhi[warp] = hi; }
    __syncthreads();
    if (tid == 0) {
        float l = 0.f, h = 0.f;
        for (int i = 0; i < 8; i++) { l += redlo[i]; h += redhi[i]; }
        Prow[0] = l;
        Prow[64] = h;
    }
}

// ---------------------------------------------------------------------------
// PV: Heads[b*T+t, h*64+d] = sum_s P[bh, t, s] * vW[bh, s, d]
// Per-batch NN GEMM M=1024, N=64, K=1024. 128x64 tiles, 8x4 micro.
// ---------------------------------------------------------------------------
__global__ __launch_bounds__(256) void pv_gemm(const float* __restrict__ P,
                                               const float* __restrict__ V,
                                               float* __restrict__ Heads)
{
    const int bh = blockIdx.y;
    const int b = bh >> 4, h = bh & 15;
    const float* Pp = P + (size_t)bh * TT * TT;
    const float* Vv = V + (size_t)bh * TT * DKK;
    float* Hp = Heads + (size_t)b * TT * DM + h * DKK;

    const int bm = blockIdx.x * 128;
    const int tid = threadIdx.x;
    const int ty = tid >> 4, tx = tid & 15;

    __shared__ float As[8][128];
    __shared__ float Bs[8][64];

    float acc[8][4];
#pragma unroll
    for (int i = 0; i < 8; i++)
#pragma unroll
        for (int j = 0; j < 4; j++) acc[i][j] = 0.f;

    const int rowA = tid >> 1;
    const int c4A  = (tid & 1) * 4;
    const int kB   = tid >> 5;
    const int n2B  = (tid & 31) * 2;

    for (int k0 = 0; k0 < TT; k0 += 8) {
        float4 a = *(const float4*)&Pp[(size_t)(bm + rowA) * TT + k0 + c4A];
        As[c4A + 0][rowA] = a.x;
        As[c4A + 1][rowA] = a.y;
        As[c4A + 2][rowA] = a.z;
        As[c4A + 3][rowA] = a.w;
        float2 bv = *(const float2*)&Vv[(size_t)(k0 + kB) * DKK + n2B];
        Bs[kB][n2B]     = bv.x;
        Bs[kB][n2B + 1] = bv.y;
        __syncthreads();
#pragma unroll
        for (int kk = 0; kk < 8; kk++) {
            float ra[8], rb[4];
#pragma unroll
            for (int i = 0; i < 8; i++) ra[i] = As[kk][ty * 8 + i];
#pragma unroll
            for (int j = 0; j < 4; j++) rb[j] = Bs[kk][tx * 4 + j];
#pragma unroll
            for (int i = 0; i < 8; i++)
#pragma unroll
                for (int j = 0; j < 4; j++) acc[i][j] += ra[i] * rb[j];
        }
        __syncthreads();
    }

#pragma unroll
    for (int i = 0; i < 8; i++) {
        int trow = bm + ty * 8 + i;
        float4 v = make_float4(acc[i][0], acc[i][1], acc[i][2], acc[i][3]);
        *(float4*)&Hp[(size_t)trow * DM + tx * 4] = v;
    }
}

// ---------------------------------------------------------------------------
// Heads += Pr @ emb_S  (65-wide contraction). 4 rows per block.
// ---------------------------------------------------------------------------
__global__ __launch_bounds__(256) void rels_add(const float* __restrict__ Pr,
                                                const float* __restrict__ embS,
                                                float* __restrict__ Heads)
{
    __shared__ float sE[NREL][DKK];
    __shared__ float sP[4][NREL];
    const int tid = threadIdx.x;
    for (int i = tid; i < NREL * DKK; i += 256) sE[i >> 6][i & 63] = embS[i];
    const size_t row0 = (size_t)blockIdx.x * 4;
    for (int i = tid; i < 4 * NREL; i += 256) sP[i / NREL][i % NREL] = Pr[row0 * NREL + i];
    __syncthreads();

    const int rl = tid >> 6;
    const int d  = tid & 63;
    const size_t row = row0 + rl;
    const int bh = (int)(row >> 10);
    const int t  = (int)(row & 1023);
    const int b = bh >> 4, h = bh & 15;

    float acc = 0.f;
#pragma unroll
    for (int r = 0; r < NREL; r++) acc += sP[rl][r] * sE[r][d];
    Heads[((size_t)b * TT + t) * DM + h * DKK + d] += acc;
}

// ---------------------------------------------------------------------------
extern "C" void kernel_launch(void* const* d_in, const int* in_sizes, int n_in,
                              void* d_out, int out_size)
{
    const float* q  = (const float*)d_in[0];
    const float* v  = (const float*)d_in[1];
    const float* WQ = (const float*)d_in[2];
    const float* WK = (const float*)d_in[3];
    const float* WV = (const float*)d_in[4];
    const float* WO = (const float*)d_in[5];
    const float* eQ = (const float*)d_in[6];
    const float* eS = (const float*)d_in[7];
    float* out = (float*)d_out;

    float *qW, *kW, *vW, *sc, *R, *Pr, *hd;
    cudaGetSymbolAddress((void**)&qW, g_qW);
    cudaGetSymbolAddress((void**)&kW, g_kW);
    cudaGetSymbolAddress((void**)&vW, g_vW);
    cudaGetSymbolAddress((void**)&sc, g_scores);
    cudaGetSymbolAddress((void**)&R,  g_R);
    cudaGetSymbolAddress((void**)&Pr, g_Pr);
    cudaGetSymbolAddress((void**)&hd, g_heads);

    proj_gemm<<<dim3(8, 32), 256>>>(q, WQ, qW);
    proj_gemm<<<dim3(8, 32), 256>>>(v, WK, kW);
    proj_gemm<<<dim3(8, 32), 256>>>(v, WV, vW);
    r_gemm<<<BH * TT / 8, 256>>>(qW, eQ, R);
    scores_gemm<<<dim3(8, 8, BH), 256>>>(qW, kW, R, sc);
    softmax_kernel<<<BH * TT, 256>>>(sc, Pr);
    pv_gemm<<<dim3(8, BH), 256>>>(sc, vW, hd);
    rels_add<<<BH * TT / 4, 256>>>(Pr, eS, hd);
    out_gemm<<<dim3(8, 32), 256>>>(hd, WO, out);
}

// round 5
// speedup vs baseline: 1.6744x; 1.6744x over previous
#include <cuda_runtime.h>
#include <math.h>
#include <stdint.h>

#define TT    1024
#define BB    4
#define HH    16
#define DKK   64
#define DM    1024
#define BH    (BB*HH)      // 64
#define NROWS (BB*TT)      // 4096
#define NREL  65

// ---------------- scratch (device globals; no allocation allowed) ----------
__device__ float g_qW[BH * TT * DKK];            // 16 MB
__device__ float g_kW[BH * TT * DKK];            // 16 MB
__device__ float g_vW[BH * TT * DKK];            // 16 MB
__device__ float g_scores[(size_t)BH * TT * TT]; // 256 MB
__device__ float g_R[BH * TT * NREL];            // 17 MB
__device__ float g_Pr[BH * TT * NREL];           // 17 MB
__device__ float g_heads[NROWS * DM];            // 16 MB

// ---------------------------------------------------------------------------
// TF32 helpers
// ---------------------------------------------------------------------------
__device__ __forceinline__ float f2tf(float x) {
    uint32_t u;
    asm("cvt.rna.tf32.f32 %0, %1;" : "=r"(u) : "f"(x));
    return __uint_as_float(u);
}

__device__ __forceinline__ void mma_tf32(float c[4],
                                         uint32_t a0, uint32_t a1, uint32_t a2, uint32_t a3,
                                         uint32_t b0, uint32_t b1)
{
    asm volatile(
        "mma.sync.aligned.m16n8k8.row.col.f32.tf32.tf32.f32 "
        "{%0,%1,%2,%3}, {%4,%5,%6,%7}, {%8,%9}, {%0,%1,%2,%3};"
        : "+f"(c[0]), "+f"(c[1]), "+f"(c[2]), "+f"(c[3])
        : "r"(a0), "r"(a1), "r"(a2), "r"(a3), "r"(b0), "r"(b1));
}

#define PADA 36     // 128 x 32 A tile, row stride 36 floats (conflict-free frag reads)
#define PADB 136    // 32 x 128 B tile, row stride 136 floats
#define PADB2 72    // 32 x 64  B tile, row stride 72 floats

// ===========================================================================
// Fused projection GEMM (tf32): for which in {Q,K,V}
//   Out[(b,h),t,d] = sum_m X[b*T+t, m] * W[h, m, d]
// grid (8, 32, 3), block 256. Block tile 128x128x32.
// ===========================================================================
__global__ __launch_bounds__(256) void proj3_tf32(const float* __restrict__ Q,
                                                  const float* __restrict__ V,
                                                  const float* __restrict__ WQ,
                                                  const float* __restrict__ WK,
                                                  const float* __restrict__ WV)
{
    __shared__ float As[128][PADA];
    __shared__ float Bs[32][PADB];

    const int which = blockIdx.z;
    const float* X = (which == 0) ? Q : V;
    const float* W = (which == 0) ? WQ : ((which == 1) ? WK : WV);
    float* Out = (which == 0) ? g_qW : ((which == 1) ? g_kW : g_vW);

    const int bm = blockIdx.y * 128;
    const int bn = blockIdx.x * 128;
    const int tid = threadIdx.x;

    // loader mapping
    const int ra  = tid & 127;            // A row 0..127
    const int kca = (tid >> 7) * 16;      // A k-base 0 or 16
    const int kb  = tid >> 3;             // B k 0..31
    const int ncb = (tid & 7) * 16;       // B n-base
    const int hB  = (bn + ncb) >> 6;
    const int dB  = (bn + ncb) & 63;

    // warp mapping
    const int warp = tid >> 5, lane = tid & 31;
    const int g = lane >> 2, c = lane & 3;
    const int wm = (warp >> 2) * 64;
    const int wn = (warp & 3) * 32;

    float acc[4][4][4];
#pragma unroll
    for (int i = 0; i < 4; i++)
#pragma unroll
        for (int j = 0; j < 4; j++)
#pragma unroll
            for (int e = 0; e < 4; e++) acc[i][j][e] = 0.f;

    float4 arg[4], brg[4];

#define PROJ_LOAD(K0)                                                          \
    {                                                                          \
        _Pragma("unroll")                                                      \
        for (int j = 0; j < 4; j++)                                            \
            arg[j] = *(const float4*)&X[(size_t)(bm + ra) * DM + (K0) + kca + 4*j]; \
        _Pragma("unroll")                                                      \
        for (int j = 0; j < 4; j++)                                            \
            brg[j] = *(const float4*)&W[((size_t)hB * DM + ((K0) + kb)) * DKK + dB + 4*j]; \
    }

#define TILE_STORE_AB()                                                        \
    {                                                                          \
        _Pragma("unroll")                                                      \
        for (int j = 0; j < 4; j++) {                                          \
            float4 t = arg[j];                                                 \
            t.x = f2tf(t.x); t.y = f2tf(t.y); t.z = f2tf(t.z); t.w = f2tf(t.w);\
            *(float4*)&As[ra][kca + 4*j] = t;                                  \
        }                                                                      \
        _Pragma("unroll")                                                      \
        for (int j = 0; j < 4; j++) {                                          \
            float4 t = brg[j];                                                 \
            t.x = f2tf(t.x); t.y = f2tf(t.y); t.z = f2tf(t.z); t.w = f2tf(t.w);\
            *(float4*)&Bs[kb][ncb + 4*j] = t;                                  \
        }                                                                      \
    }

#define TILE_COMPUTE_44()                                                      \
    {                                                                          \
        _Pragma("unroll")                                                      \
        for (int kk = 0; kk < 4; kk++) {                                       \
            const int kbs = kk * 8;                                            \
            uint32_t af[4][4], bf[4][2];                                       \
            _Pragma("unroll")                                                  \
            for (int mt = 0; mt < 4; mt++) {                                   \
                const int rm = wm + mt * 16;                                   \
                af[mt][0] = __float_as_uint(As[rm + g    ][kbs + c    ]);      \
                af[mt][1] = __float_as_uint(As[rm + g + 8][kbs + c    ]);      \
                af[mt][2] = __float_as_uint(As[rm + g    ][kbs + c + 4]);      \
                af[mt][3] = __float_as_uint(As[rm + g + 8][kbs + c + 4]);      \
            }                                                                  \
            _Pragma("unroll")                                                  \
            for (int nt = 0; nt < 4; nt++) {                                   \
                bf[nt][0] = __float_as_uint(Bs[kbs + c    ][wn + nt * 8 + g]); \
                bf[nt][1] = __float_as_uint(Bs[kbs + c + 4][wn + nt * 8 + g]); \
            }                                                                  \
            _Pragma("unroll")                                                  \
            for (int mt = 0; mt < 4; mt++)                                     \
                _Pragma("unroll")                                              \
                for (int nt = 0; nt < 4; nt++)                                 \
                    mma_tf32(acc[mt][nt], af[mt][0], af[mt][1], af[mt][2],     \
                             af[mt][3], bf[nt][0], bf[nt][1]);                 \
        }                                                                      \
    }

    PROJ_LOAD(0);
    TILE_STORE_AB();
    __syncthreads();
    for (int k0 = 32; k0 < DM; k0 += 32) {
        PROJ_LOAD(k0);
        TILE_COMPUTE_44();
        __syncthreads();
        TILE_STORE_AB();
        __syncthreads();
    }
    TILE_COMPUTE_44();

    // epilogue: scatter to (bh, t, d)
    const int bglob = bm >> 10;   // whole block within one batch (1024 % 128 == 0)
#pragma unroll
    for (int mt = 0; mt < 4; mt++) {
#pragma unroll
        for (int nt = 0; nt < 4; nt++) {
            int t0 = bm + wm + mt * 16 + g;
            int n0 = bn + wn + nt * 8 + c * 2;
            int h = n0 >> 6, d = n0 & 63;
            size_t base = ((size_t)(bglob * HH + h) * TT) * DKK + d;
            *(float2*)&Out[base + (size_t)(t0 & 1023) * DKK] =
                make_float2(acc[mt][nt][0], acc[mt][nt][1]);
            *(float2*)&Out[base + (size_t)((t0 + 8) & 1023) * DKK] =
                make_float2(acc[mt][nt][2], acc[mt][nt][3]);
        }
    }
}

// ===========================================================================
// Scores (tf32): S[bh,t,s] = (qW[t,:]·kW[s,:] + R[bh,t,rel]) / 8
// NT GEMM per head: grid (8, 8, 64), K = 64.
// ===========================================================================
__global__ __launch_bounds__(256) void scores_tf32(const float* __restrict__ Qw,
                                                   const float* __restrict__ Kw,
                                                   const float* __restrict__ R,
                                                   float* __restrict__ S)
{
    __shared__ float As[128][PADA];
    __shared__ float Bs[32][PADB];

    const int bh = blockIdx.z;
    const float* Aq = Qw + (size_t)bh * TT * DKK;
    const float* Bk = Kw + (size_t)bh * TT * DKK;
    float*       Sc = S  + (size_t)bh * TT * TT;
    const float* Rb = R  + (size_t)bh * TT * NREL;

    const int bm = blockIdx.y * 128;
    const int bn = blockIdx.x * 128;
    const int tid = threadIdx.x;

    const int ra  = tid & 127;
    const int kca = (tid >> 7) * 16;

    const int warp = tid >> 5, lane = tid & 31;
    const int g = lane >> 2, c = lane & 3;
    const int wm = (warp >> 2) * 64;
    const int wn = (warp & 3) * 32;

    float acc[4][4][4];
#pragma unroll
    for (int i = 0; i < 4; i++)
#pragma unroll
        for (int j = 0; j < 4; j++)
#pragma unroll
            for (int e = 0; e < 4; e++) acc[i][j][e] = 0.f;

    float4 arg[4], brg[4];

#define SC_LOAD(K0)                                                            \
    {                                                                          \
        _Pragma("unroll")                                                      \
        for (int j = 0; j < 4; j++)                                            \
            arg[j] = *(const float4*)&Aq[(size_t)(bm + ra) * DKK + (K0) + kca + 4*j]; \
        _Pragma("unroll")                                                      \
        for (int j = 0; j < 4; j++)                                            \
            brg[j] = *(const float4*)&Bk[(size_t)(bn + ra) * DKK + (K0) + kca + 4*j]; \
    }

#define SC_STORE()                                                             \
    {                                                                          \
        _Pragma("unroll")                                                      \
        for (int j = 0; j < 4; j++) {                                          \
            float4 t = arg[j];                                                 \
            t.x = f2tf(t.x); t.y = f2tf(t.y); t.z = f2tf(t.z); t.w = f2tf(t.w);\
            *(float4*)&As[ra][kca + 4*j] = t;                                  \
        }                                                                      \
        _Pragma("unroll")                                                      \
        for (int j = 0; j < 4; j++) {  /* transpose B into [k][n] */           \
            Bs[kca + 4*j + 0][ra] = f2tf(brg[j].x);                            \
            Bs[kca + 4*j + 1][ra] = f2tf(brg[j].y);                            \
            Bs[kca + 4*j + 2][ra] = f2tf(brg[j].z);                            \
            Bs[kca + 4*j + 3][ra] = f2tf(brg[j].w);                            \
        }                                                                      \
    }

    SC_LOAD(0);
    SC_STORE();
    __syncthreads();
    SC_LOAD(32);
    TILE_COMPUTE_44();
    __syncthreads();
    SC_STORE();
    __syncthreads();
    TILE_COMPUTE_44();

    // epilogue: add relative bias, scale, store
#pragma unroll
    for (int mt = 0; mt < 4; mt++) {
#pragma unroll
        for (int nt = 0; nt < 4; nt++) {
            int t0 = bm + wm + mt * 16 + g;
            int s0 = bn + wn + nt * 8 + c * 2;
#pragma unroll
            for (int e = 0; e < 4; e++) {
                int t = t0 + (e >> 1) * 8;
                int s = s0 + (e & 1);
                int rr = s - t;
                rr = min(max(rr, -32), 32) + 32;
                Sc[(size_t)t * TT + s] = (acc[mt][nt][e] + __ldg(&Rb[t * NREL + rr])) * 0.125f;
            }
        }
    }
}

// ===========================================================================
// PV (tf32): Heads[b*T+t, h*64+d] = sum_s P[bh,t,s] * vW[bh,s,d]
// grid (8, 64). Block tile 128x64x32; warp tile 32x32.
// ===========================================================================
__global__ __launch_bounds__(256) void pv_tf32(const float* __restrict__ P,
                                               const float* __restrict__ V,
                                               float* __restrict__ Heads)
{
    __shared__ float As[128][PADA];
    __shared__ float Bs[32][PADB2];

    const int bh = blockIdx.y;
    const int b = bh >> 4, h = bh & 15;
    const float* Pp = P + (size_t)bh * TT * TT;
    const float* Vv = V + (size_t)bh * TT * DKK;
    float* Hp = Heads + (size_t)b * TT * DM + h * DKK;

    const int bm = blockIdx.x * 128;
    const int tid = threadIdx.x;

    const int ra  = tid & 127;
    const int kca = (tid >> 7) * 16;
    const int kb  = tid >> 3;             // 0..31
    const int ncb = (tid & 7) * 8;        // 0..56

    const int warp = tid >> 5, lane = tid & 31;
    const int g = lane >> 2, c = lane & 3;
    const int wm = (warp >> 1) * 32;      // 4 warp-rows
    const int wn = (warp & 1) * 32;       // 2 warp-cols

    float acc[2][4][4];
#pragma unroll
    for (int i = 0; i < 2; i++)
#pragma unroll
        for (int j = 0; j < 4; j++)
#pragma unroll
            for (int e = 0; e < 4; e++) acc[i][j][e] = 0.f;

    float4 arg[4], brg[2];

#define PV_LOAD(K0)                                                            \
    {                                                                          \
        _Pragma("unroll")                                                      \
        for (int j = 0; j < 4; j++)                                            \
            arg[j] = *(const float4*)&Pp[(size_t)(bm + ra) * TT + (K0) + kca + 4*j]; \
        _Pragma("unroll")                                                      \
        for (int j = 0; j < 2; j++)                                            \
            brg[j] = *(const float4*)&Vv[(size_t)((K0) + kb) * DKK + ncb + 4*j]; \
    }

#define PV_STORE()                                                             \
    {                                                                          \
        _Pragma("unroll")                                                      \
        for (int j = 0; j < 4; j++) {                                          \
            float4 t = arg[j];                                                 \
            t.x = f2tf(t.x); t.y = f2tf(t.y); t.z = f2tf(t.z); t.w = f2tf(t.w);\
            *(float4*)&As[ra][kca + 4*j] = t;                                  \
        }                                                                      \
        _Pragma("unroll")                                                      \
        for (int j = 0; j < 2; j++) {                                          \
            float4 t = brg[j];                                                 \
            t.x = f2tf(t.x); t.y = f2tf(t.y); t.z = f2tf(t.z); t.w = f2tf(t.w);\
            *(float4*)&Bs[kb][ncb + 4*j] = t;                                  \
        }                                                                      \
    }

#define PV_COMPUTE()                                                           \
    {                                                                          \
        _Pragma("unroll")                                                      \
        for (int kk = 0; kk < 4; kk++) {                                       \
            const int kbs = kk * 8;                                            \
            uint32_t af[2][4], bf[4][2];                                       \
            _Pragma("unroll")                                                  \
            for (int mt = 0; mt < 2; mt++) {                                   \
                const int rm = wm + mt * 16;                                   \
                af[mt][0] = __float_as_uint(As[rm + g    ][kbs + c    ]);      \
                af[mt][1] = __float_as_uint(As[rm + g + 8][kbs + c    ]);      \
                af[mt][2] = __float_as_uint(As[rm + g    ][kbs + c + 4]);      \
                af[mt][3] = __float_as_uint(As[rm + g + 8][kbs + c + 4]);      \
            }                                                                  \
            _Pragma("unroll")                                                  \
            for (int nt = 0; nt < 4; nt++) {                                   \
                bf[nt][0] = __float_as_uint(Bs[kbs + c    ][wn + nt * 8 + g]); \
                bf[nt][1] = __float_as_uint(Bs[kbs + c + 4][wn + nt * 8 + g]); \
            }                                                                  \
            _Pragma("unroll")                                                  \
            for (int mt = 0; mt < 2; mt++)                                     \
                _Pragma("unroll")                                              \
                for (int nt = 0; nt < 4; nt++)                                 \
                    mma_tf32(acc[mt][nt], af[mt][0], af[mt][1], af[mt][2],     \
                             af[mt][3], bf[nt][0], bf[nt][1]);                 \
        }                                                                      \
    }

    PV_LOAD(0);
    PV_STORE();
    __syncthreads();
    for (int k0 = 32; k0 < TT; k0 += 32) {
        PV_LOAD(k0);
        PV_COMPUTE();
        __syncthreads();
        PV_STORE();
        __syncthreads();
    }
    PV_COMPUTE();

#pragma unroll
    for (int mt = 0; mt < 2; mt++) {
#pragma unroll
        for (int nt = 0; nt < 4; nt++) {
            int t0 = bm + wm + mt * 16 + g;
            int n0 = wn + nt * 8 + c * 2;
            *(float2*)&Hp[(size_t)t0 * DM + n0] =
                make_float2(acc[mt][nt][0], acc[mt][nt][1]);
            *(float2*)&Hp[(size_t)(t0 + 8) * DM + n0] =
                make_float2(acc[mt][nt][2], acc[mt][nt][3]);
        }
    }
}

// ===========================================================================
// Output GEMM (tf32): C[n, m] = sum_k A[n,k] * Bm[k,m]; 4096x1024x1024.
// ===========================================================================
__global__ __launch_bounds__(256) void out_tf32(const float* __restrict__ A,
                                                const float* __restrict__ Bm,
                                                float* __restrict__ C)
{
    __shared__ float As[128][PADA];
    __shared__ float Bs[32][PADB];

    const int bm = blockIdx.y * 128;
    const int bn = blockIdx.x * 128;
    const int tid = threadIdx.x;

    const int ra  = tid & 127;
    const int kca = (tid >> 7) * 16;
    const int kb  = tid >> 3;
    const int ncb = (tid & 7) * 16;

    const int warp = tid >> 5, lane = tid & 31;
    const int g = lane >> 2, c = lane & 3;
    const int wm = (warp >> 2) * 64;
    const int wn = (warp & 3) * 32;

    float acc[4][4][4];
#pragma unroll
    for (int i = 0; i < 4; i++)
#pragma unroll
        for (int j = 0; j < 4; j++)
#pragma unroll
            for (int e = 0; e < 4; e++) acc[i][j][e] = 0.f;

    float4 arg[4], brg[4];

#define OUT_LOAD(K0)                                                           \
    {                                                                          \
        _Pragma("unroll")                                                      \
        for (int j = 0; j < 4; j++)                                            \
            arg[j] = *(const float4*)&A[(size_t)(bm + ra) * DM + (K0) + kca + 4*j]; \
        _Pragma("unroll")                                                      \
        for (int j = 0; j < 4; j++)                                            \
            brg[j] = *(const float4*)&Bm[(size_t)((K0) + kb) * DM + bn + ncb + 4*j]; \
    }

    OUT_LOAD(0);
    TILE_STORE_AB();
    __syncthreads();
    for (int k0 = 32; k0 < DM; k0 += 32) {
        OUT_LOAD(k0);
        TILE_COMPUTE_44();
        __syncthreads();
        TILE_STORE_AB();
        __syncthreads();
    }
    TILE_COMPUTE_44();

#pragma unroll
    for (int mt = 0; mt < 4; mt++) {
#pragma unroll
        for (int nt = 0; nt < 4; nt++) {
            int t0 = bm + wm + mt * 16 + g;
            int n0 = bn + wn + nt * 8 + c * 2;
            *(float2*)&C[(size_t)t0 * DM + n0] =
                make_float2(acc[mt][nt][0], acc[mt][nt][1]);
            *(float2*)&C[(size_t)(t0 + 8) * DM + n0] =
                make_float2(acc[mt][nt][2], acc[mt][nt][3]);
        }
    }
}

// ---------------------------------------------------------------------------
// R[bh, t, r] = sum_k qW[bh, t, k] * emb_Q[r, k].  One warp per row. (fp32)
// ---------------------------------------------------------------------------
__global__ __launch_bounds__(256) void r_gemm(const float* __restrict__ Q,
                                              const float* __restrict__ embQ,
                                              float* __restrict__ R)
{
    __shared__ float sE[NREL][DKK + 1];
    __shared__ float sQ[8][DKK];
    const int tid = threadIdx.x;
    for (int i = tid; i < NREL * DKK; i += 256) sE[i >> 6][i & 63] = embQ[i];
    const int warp = tid >> 5, lane = tid & 31;
    const size_t row = (size_t)blockIdx.x * 8 + warp;
    sQ[warp][lane]      = Q[row * DKK + lane];
    sQ[warp][lane + 32] = Q[row * DKK + lane + 32];
    __syncthreads();
    float a0 = 0.f, a1 = 0.f, a2 = 0.f;
#pragma unroll
    for (int k = 0; k < DKK; k++) {
        float q = sQ[warp][k];
        a0 += q * sE[lane][k];
        a1 += q * sE[lane + 32][k];
        a2 += q * sE[64][k];
    }
    R[row * NREL + lane]      = a0;
    R[row * NREL + lane + 32] = a1;
    if (lane == 0) R[row * NREL + 64] = a2;
}

// ---------------------------------------------------------------------------
// Row softmax (in place) + bucketed probability sums Pr[row, 0..64]. (fp32)
// ---------------------------------------------------------------------------
__global__ __launch_bounds__(256) void softmax_kernel(float* __restrict__ S,
                                                      float* __restrict__ Pr)
{
    const size_t row = blockIdx.x;
    const int t = (int)(row & (TT - 1));
    float* Sr = S + row * (size_t)TT;

    __shared__ float sp[TT];
    __shared__ float red[8];
    __shared__ float redlo[8], redhi[8];

    const int tid = threadIdx.x;
    const int lane = tid & 31, warp = tid >> 5;

    float x0 = Sr[tid], x1 = Sr[tid + 256], x2 = Sr[tid + 512], x3 = Sr[tid + 768];
    float mx = fmaxf(fmaxf(x0, x1), fmaxf(x2, x3));
#pragma unroll
    for (int o = 16; o; o >>= 1) mx = fmaxf(mx, __shfl_xor_sync(0xffffffffu, mx, o));
    if (lane == 0) red[warp] = mx;
    __syncthreads();
    mx = red[0];
#pragma unroll
    for (int i = 1; i < 8; i++) mx = fmaxf(mx, red[i]);

    x0 = __expf(x0 - mx); x1 = __expf(x1 - mx);
    x2 = __expf(x2 - mx); x3 = __expf(x3 - mx);
    float sm = x0 + x1 + x2 + x3;
#pragma unroll
    for (int o = 16; o; o >>= 1) sm += __shfl_xor_sync(0xffffffffu, sm, o);
    __syncthreads();
    if (lane == 0) red[warp] = sm;
    __syncthreads();
    sm = red[0] + red[1] + red[2] + red[3] + red[4] + red[5] + red[6] + red[7];
    float inv = 1.f / sm;
    x0 *= inv; x1 *= inv; x2 *= inv; x3 *= inv;

    sp[tid] = x0; sp[tid + 256] = x1; sp[tid + 512] = x2; sp[tid + 768] = x3;
    Sr[tid] = x0; Sr[tid + 256] = x1; Sr[tid + 512] = x2; Sr[tid + 768] = x3;
    __syncthreads();

    float* Prow = Pr + row * NREL;
    if (tid >= 1 && tid <= 63) {
        int s = t + tid - 32;
        Prow[tid] = (s >= 0 && s < TT) ? sp[s] : 0.f;
    }
    float lo = 0.f, hi = 0.f;
#pragma unroll
    for (int j = 0; j < 4; j++) {
        int s = tid + 256 * j;
        float p = sp[s];
        if (s <= t - 32) lo += p;
        if (s >= t + 32) hi += p;
    }
#pragma unroll
    for (int o = 16; o; o >>= 1) {
        lo += __shfl_xor_sync(0xffffffffu, lo, o);
        hi += __shfl_xor_sync(0xffffffffu, hi, o);
    }
    if (lane == 0) { redlo[warp] = lo; redhi[warp] = hi; }
    __syncthreads();
    if (tid == 0) {
        float l = 0.f, h = 0.f;
        for (int i = 0; i < 8; i++) { l += redlo[i]; h += redhi[i]; }
        Prow[0] = l;
        Prow[64] = h;
    }
}

// ---------------------------------------------------------------------------
// Heads += Pr @ emb_S  (65-wide contraction). 4 rows per block. (fp32)
// ---------------------------------------------------------------------------
__global__ __launch_bounds__(256) void rels_add(const float* __restrict__ Pr,
                                                const float* __restrict__ embS,
                                                float* __restrict__ Heads)
{
    __shared__ float sE[NREL][DKK];
    __shared__ float sP[4][NREL];
    const int tid = threadIdx.x;
    for (int i = tid; i < NREL * DKK; i += 256) sE[i >> 6][i & 63] = embS[i];
    const size_t row0 = (size_t)blockIdx.x * 4;
    for (int i = tid; i < 4 * NREL; i += 256) sP[i / NREL][i % NREL] = Pr[row0 * NREL + i];
    __syncthreads();

    const int rl = tid >> 6;
    const int d  = tid & 63;
    const size_t row = row0 + rl;
    const int bh = (int)(row >> 10);
    const int t  = (int)(row & 1023);
    const int b = bh >> 4, h = bh & 15;

    float acc = 0.f;
#pragma unroll
    for (int r = 0; r < NREL; r++) acc += sP[rl][r] * sE[r][d];
    Heads[((size_t)b * TT + t) * DM + h * DKK + d] += acc;
}

// ---------------------------------------------------------------------------
extern "C" void kernel_launch(void* const* d_in, const int* in_sizes, int n_in,
                              void* d_out, int out_size)
{
    const float* q  = (const float*)d_in[0];
    const float* v  = (const float*)d_in[1];
    const float* WQ = (const float*)d_in[2];
    const float* WK = (const float*)d_in[3];
    const float* WV = (const float*)d_in[4];
    const float* WO = (const float*)d_in[5];
    const float* eQ = (const float*)d_in[6];
    const float* eS = (const float*)d_in[7];
    float* out = (float*)d_out;

    float *qW, *kW, *vW, *sc, *R, *Pr, *hd;
    cudaGetSymbolAddress((void**)&qW, g_qW);
    cudaGetSymbolAddress((void**)&kW, g_kW);
    cudaGetSymbolAddress((void**)&vW, g_vW);
    cudaGetSymbolAddress((void**)&sc, g_scores);
    cudaGetSymbolAddress((void**)&R,  g_R);
    cudaGetSymbolAddress((void**)&Pr, g_Pr);
    cudaGetSymbolAddress((void**)&hd, g_heads);

    proj3_tf32<<<dim3(8, 32, 3), 256>>>(q, v, WQ, WK, WV);
    r_gemm<<<BH * TT / 8, 256>>>(qW, eQ, R);
    scores_tf32<<<dim3(8, 8, BH), 256>>>(qW, kW, R, sc);
    softmax_kernel<<<BH * TT, 256>>>(sc, Pr);
    pv_tf32<<<dim3(8, BH), 256>>>(sc, vW, hd);
    rels_add<<<BH * TT / 4, 256>>>(Pr, eS, hd);
    out_tf32<<<dim3(8, 32), 256>>>(hd, WO, out);
}

// round 9
// speedup vs baseline: 2.2083x; 1.3189x over previous
#include <cuda_runtime.h>
#include <math.h>
#include <stdint.h>

#define TT    1024
#define BB    4
#define HH    16
#define DKK   64
#define DM    1024
#define BH    (BB*HH)      // 64
#define NROWS (BB*TT)      // 4096
#define NREL  65

// ---------------- scratch (device globals; no allocation allowed) ----------
__device__ float g_qW[BH * TT * DKK];            // 16 MB
__device__ float g_kW[BH * TT * DKK];            // 16 MB
__device__ float g_vW[BH * TT * DKK];            // 16 MB
__device__ float g_heads[NROWS * DM];            // 16 MB

// ---------------------------------------------------------------------------
// TF32 helpers
// ---------------------------------------------------------------------------
__device__ __forceinline__ float f2tf(float x) {
    uint32_t u;
    asm("cvt.rna.tf32.f32 %0, %1;" : "=r"(u) : "f"(x));
    return __uint_as_float(u);
}

__device__ __forceinline__ float ex2(float x) {
    float y;
    asm("ex2.approx.f32 %0, %1;" : "=f"(y) : "f"(x));
    return y;
}

__device__ __forceinline__ void mma_tf32(float c[4],
                                         uint32_t a0, uint32_t a1, uint32_t a2, uint32_t a3,
                                         uint32_t b0, uint32_t b1)
{
    asm volatile(
        "mma.sync.aligned.m16n8k8.row.col.f32.tf32.tf32.f32 "
        "{%0,%1,%2,%3}, {%4,%5,%6,%7}, {%8,%9}, {%0,%1,%2,%3};"
        : "+f"(c[0]), "+f"(c[1]), "+f"(c[2]), "+f"(c[3])
        : "r"(a0), "r"(a1), "r"(a2), "r"(a3), "r"(b0), "r"(b1));
}

#define PADA 36     // 128 x 32 A tile, row stride 36 floats (conflict-free frag reads)
#define PADB 136    // 32 x 128 B tile, row stride 136 floats

// ===========================================================================
// Fused projection GEMM (tf32): for which in {Q,K,V}
// ===========================================================================
__global__ __launch_bounds__(256) void proj3_tf32(const float* __restrict__ Q,
                                                  const float* __restrict__ V,
                                                  const float* __restrict__ WQ,
                                                  const float* __restrict__ WK,
                                                  const float* __restrict__ WV)
{
    __shared__ float As[128][PADA];
    __shared__ float Bs[32][PADB];

    const int which = blockIdx.z;
    const float* X = (which == 0) ? Q : V;
    const float* W = (which == 0) ? WQ : ((which == 1) ? WK : WV);
    float* Out = (which == 0) ? g_qW : ((which == 1) ? g_kW : g_vW);

    const int bm = blockIdx.y * 128;
    const int bn = blockIdx.x * 128;
    const int tid = threadIdx.x;

    const int ra  = tid & 127;
    const int kca = (tid >> 7) * 16;
    const int kb  = tid >> 3;
    const int ncb = (tid & 7) * 16;
    const int hB  = (bn + ncb) >> 6;
    const int dB  = (bn + ncb) & 63;

    const int warp = tid >> 5, lane = tid & 31;
    const int g = lane >> 2, c = lane & 3;
    const int wm = (warp >> 2) * 64;
    const int wn = (warp & 3) * 32;

    float acc[4][4][4];
#pragma unroll
    for (int i = 0; i < 4; i++)
#pragma unroll
        for (int j = 0; j < 4; j++)
#pragma unroll
            for (int e = 0; e < 4; e++) acc[i][j][e] = 0.f;

    float4 arg[4], brg[4];

#define PROJ_LOAD(K0)                                                          \
    {                                                                          \
        _Pragma("unroll")                                                      \
        for (int j = 0; j < 4; j++)                                            \
            arg[j] = *(const float4*)&X[(size_t)(bm + ra) * DM + (K0) + kca + 4*j]; \
        _Pragma("unroll")                                                      \
        for (int j = 0; j < 4; j++)                                            \
            brg[j] = *(const float4*)&W[((size_t)hB * DM + ((K0) + kb)) * DKK + dB + 4*j]; \
    }

#define TILE_STORE_AB()                                                        \
    {                                                                          \
        _Pragma("unroll")                                                      \
        for (int j = 0; j < 4; j++) {                                          \
            float4 t = arg[j];                                                 \
            t.x = f2tf(t.x); t.y = f2tf(t.y); t.z = f2tf(t.z); t.w = f2tf(t.w);\
            *(float4*)&As[ra][kca + 4*j] = t;                                  \
        }                                                                      \
        _Pragma("unroll")                                                      \
        for (int j = 0; j < 4; j++) {                                          \
            float4 t = brg[j];                                                 \
            t.x = f2tf(t.x); t.y = f2tf(t.y); t.z = f2tf(t.z); t.w = f2tf(t.w);\
            *(float4*)&Bs[kb][ncb + 4*j] = t;                                  \
        }                                                                      \
    }

#define TILE_COMPUTE_44()                                                      \
    {                                                                          \
        _Pragma("unroll")                                                      \
        for (int kk = 0; kk < 4; kk++) {                                       \
            const int kbs = kk * 8;                                            \
            uint32_t af[4][4], bf[4][2];                                       \
            _Pragma("unroll")                                                  \
            for (int mt = 0; mt < 4; mt++) {                                   \
                const int rm = wm + mt * 16;                                   \
                af[mt][0] = __float_as_uint(As[rm + g    ][kbs + c    ]);      \
                af[mt][1] = __float_as_uint(As[rm + g + 8][kbs + c    ]);      \
                af[mt][2] = __float_as_uint(As[rm + g    ][kbs + c + 4]);      \
                af[mt][3] = __float_as_uint(As[rm + g + 8][kbs + c + 4]);      \
            }                                                                  \
            _Pragma("unroll")                                                  \
            for (int nt = 0; nt < 4; nt++) {                                   \
                bf[nt][0] = __float_as_uint(Bs[kbs + c    ][wn + nt * 8 + g]); \
                bf[nt][1] = __float_as_uint(Bs[kbs + c + 4][wn + nt * 8 + g]); \
            }                                                                  \
            _Pragma("unroll")                                                  \
            for (int mt = 0; mt < 4; mt++)                                     \
                _Pragma("unroll")                                              \
                for (int nt = 0; nt < 4; nt++)                                 \
                    mma_tf32(acc[mt][nt], af[mt][0], af[mt][1], af[mt][2],     \
                             af[mt][3], bf[nt][0], bf[nt][1]);                 \
        }                                                                      \
    }

    PROJ_LOAD(0);
    TILE_STORE_AB();
    __syncthreads();
    for (int k0 = 32; k0 < DM; k0 += 32) {
        PROJ_LOAD(k0);
        TILE_COMPUTE_44();
        __syncthreads();
        TILE_STORE_AB();
        __syncthreads();
    }
    TILE_COMPUTE_44();

    const int bglob = bm >> 10;
#pragma unroll
    for (int mt = 0; mt < 4; mt++) {
#pragma unroll
        for (int nt = 0; nt < 4; nt++) {
            int t0 = bm + wm + mt * 16 + g;
            int n0 = bn + wn + nt * 8 + c * 2;
            int h = n0 >> 6, d = n0 & 63;
            size_t base = ((size_t)(bglob * HH + h) * TT) * DKK + d;
            *(float2*)&g_qW[0]; // no-op to silence nothing
            *(float2*)&Out[base + (size_t)(t0 & 1023) * DKK] =
                make_float2(acc[mt][nt][0], acc[mt][nt][1]);
            *(float2*)&Out[base + (size_t)((t0 + 8) & 1023) * DKK] =
                make_float2(acc[mt][nt][2], acc[mt][nt][3]);
        }
    }
}

// ===========================================================================
// Fused flash attention with relative position terms.
// Block = 128 query rows x 1 head. Dynamic smem layout (floats):
// ===========================================================================
#define SM_AS   0                    // As[128][68]  Q tile tf32
#define SM_KS   8704                 // Ks[32][136]  K chunk (k-major)
#define SM_VS   13056                // Vs[32][72]   V chunk
#define SM_RS   15360                // RS[128][66]  relative-Q bias table
#define SM_PR   23808                // PrS[128][66] bucketed prob sums
#define SM_RF   32256                // rowF[128]    rescale factors
#define SM_E64  32384                // E64[64]      emb_Q row 64
#define SM_LH   32448                // LH[128][4]   lo/hi partials
#define SM_PS   32960                // Ps[128][132] P tile (overlays Et / Es)
#define SM_FTOT 49856
#define ATTN_SMEM_BYTES (SM_FTOT * 4)

__global__ __launch_bounds__(256, 1) void attn_fused(const float* __restrict__ embQ,
                                                     const float* __restrict__ embS)
{
    extern __shared__ float sm[];
    float* As   = sm + SM_AS;    // stride 68
    float* Ks   = sm + SM_KS;    // stride 136
    float* Vs   = sm + SM_VS;    // stride 72
    float* RS   = sm + SM_RS;    // stride 66
    float* PrS  = sm + SM_PR;    // stride 66
    float* rowF = sm + SM_RF;
    float* E64  = sm + SM_E64;
    float* LH   = sm + SM_LH;    // stride 4
    float* Ps   = sm + SM_PS;    // stride 132

    const int bh = blockIdx.y;
    const int bm = blockIdx.x * 128;
    const float* Qb = g_qW + (size_t)bh * TT * DKK;
    const float* Kb = g_kW + (size_t)bh * TT * DKK;
    const float* Vb = g_vW + (size_t)bh * TT * DKK;

    const int tid  = threadIdx.x;
    const int warp = tid >> 5, lane = tid & 31;
    const int g = lane >> 2, c = lane & 3;
    const int r0 = warp * 16 + g;     // local query row (this thread)
    const int r1 = r0 + 8;

    // ---------- prologue: load Q tile (tf32, coalesced) ----------
#pragma unroll
    for (int rep = 0; rep < 4; rep++) {
        int idx = rep * 2048 + tid * 8;
        int row = idx >> 6, col = idx & 63;
        float4 v0 = *(const float4*)&Qb[(size_t)bm * DKK + idx];
        float4 v1 = *(const float4*)&Qb[(size_t)bm * DKK + idx + 4];
        v0.x = f2tf(v0.x); v0.y = f2tf(v0.y); v0.z = f2tf(v0.z); v0.w = f2tf(v0.w);
        v1.x = f2tf(v1.x); v1.y = f2tf(v1.y); v1.z = f2tf(v1.z); v1.w = f2tf(v1.w);
        *(float4*)&As[row * 68 + col]     = v0;
        *(float4*)&As[row * 68 + col + 4] = v1;
    }
    // emb_Q transposed (rows 0..63) into Ps region; row 64 separately
    {
        float* Et = Ps;  // [64][68]
        for (int i = tid; i < 4096; i += 256) {
            int k = i & 63, r = i >> 6;
            Et[k * 68 + r] = f2tf(embQ[r * 64 + k]);
        }
        if (tid < 64) E64[tid] = embQ[64 * 64 + tid];
    }
    for (int i = tid; i < 128 * 66; i += 256) PrS[i] = 0.f;
    __syncthreads();

    // ---------- RS[t][0..63] = Q_tile @ emb_Q^T via MMA ----------
    {
        float* Et = Ps;
        float racc[8][4];
#pragma unroll
        for (int nt = 0; nt < 8; nt++)
#pragma unroll
            for (int e = 0; e < 4; e++) racc[nt][e] = 0.f;
#pragma unroll
        for (int kk = 0; kk < 8; kk++) {
            uint32_t a0 = __float_as_uint(As[r0 * 68 + kk * 8 + c]);
            uint32_t a1 = __float_as_uint(As[r1 * 68 + kk * 8 + c]);
            uint32_t a2 = __float_as_uint(As[r0 * 68 + kk * 8 + c + 4]);
            uint32_t a3 = __float_as_uint(As[r1 * 68 + kk * 8 + c + 4]);
#pragma unroll
            for (int nt = 0; nt < 8; nt++) {
                uint32_t b0 = __float_as_uint(Et[(kk * 8 + c) * 68 + nt * 8 + g]);
                uint32_t b1 = __float_as_uint(Et[(kk * 8 + c + 4) * 68 + nt * 8 + g]);
                mma_tf32(racc[nt], a0, a1, a2, a3, b0, b1);
            }
        }
#pragma unroll
        for (int nt = 0; nt < 8; nt++) {
            *(float2*)&RS[r0 * 66 + nt * 8 + 2 * c] = make_float2(racc[nt][0], racc[nt][1]);
            *(float2*)&RS[r1 * 66 + nt * 8 + 2 * c] = make_float2(racc[nt][2], racc[nt][3]);
        }
    }
    if (tid < 128) {     // r = 64 column (plain dot)
        float a = 0.f;
#pragma unroll
        for (int k = 0; k < 64; k++) a += As[tid * 68 + k] * E64[k];
        RS[tid * 66 + 64] = a;
    }

    // online softmax state (per thread: rows r0, r1)
    float m0 = -INFINITY, m1 = -INFINITY, l0 = 0.f, l1 = 0.f;
    float oacc[8][4];
#pragma unroll
    for (int nt = 0; nt < 8; nt++)
#pragma unroll
        for (int e = 0; e < 4; e++) oacc[nt][e] = 0.f;

    const float SCL = 0.125f * 1.4426950408889634f;  // (1/sqrt(64)) * log2(e)
    const int t0 = bm + r0, t1 = bm + r1;
    __syncthreads();     // RS / PrS ready; Et region free for Ps

    // =============== main loop over key tiles ===============
    for (int it = 0; it < 8; it++) {
        const int bn = it * 128;
        float sacc[16][4];
#pragma unroll
        for (int nt = 0; nt < 16; nt++)
#pragma unroll
            for (int e = 0; e < 4; e++) sacc[nt][e] = 0.f;

        // ---- S = Q K^T over k=64 in two 32-chunks ----
#pragma unroll
        for (int kc = 0; kc < 64; kc += 32) {
            {
                int s = tid & 127, kh = (tid >> 7) * 16;
                const float* src = &Kb[(size_t)(bn + s) * DKK + kc + kh];
#pragma unroll
                for (int j = 0; j < 4; j++) {
                    float4 v = *(const float4*)&src[4 * j];
                    Ks[(kh + 4 * j + 0) * 136 + s] = f2tf(v.x);
                    Ks[(kh + 4 * j + 1) * 136 + s] = f2tf(v.y);
                    Ks[(kh + 4 * j + 2) * 136 + s] = f2tf(v.z);
                    Ks[(kh + 4 * j + 3) * 136 + s] = f2tf(v.w);
                }
            }
            __syncthreads();
#pragma unroll
            for (int kk = 0; kk < 4; kk++) {
                int kb = kc + kk * 8;
                uint32_t a0 = __float_as_uint(As[r0 * 68 + kb + c]);
                uint32_t a1 = __float_as_uint(As[r1 * 68 + kb + c]);
                uint32_t a2 = __float_as_uint(As[r0 * 68 + kb + c + 4]);
                uint32_t a3 = __float_as_uint(As[r1 * 68 + kb + c + 4]);
#pragma unroll
                for (int nt = 0; nt < 16; nt++) {
                    uint32_t b0 = __float_as_uint(Ks[(kk * 8 + c) * 136 + nt * 8 + g]);
                    uint32_t b1 = __float_as_uint(Ks[(kk * 8 + c + 4) * 136 + nt * 8 + g]);
                    mma_tf32(sacc[nt], a0, a1, a2, a3, b0, b1);
                }
            }
            __syncthreads();
        }

        // ---- epilogue: bias + scale (base-2), online softmax ----
        float tm0 = -INFINITY, tm1 = -INFINITY;
#pragma unroll
        for (int nt = 0; nt < 16; nt++) {
            int s0 = bn + nt * 8 + 2 * c;
            int d0 = min(max(s0 - t0, -32), 32) + 32;
            int d1 = min(max(s0 + 1 - t0, -32), 32) + 32;
            int d2 = min(max(s0 - t1, -32), 32) + 32;
            int d3 = min(max(s0 + 1 - t1, -32), 32) + 32;
            sacc[nt][0] = (sacc[nt][0] + RS[r0 * 66 + d0]) * SCL;
            sacc[nt][1] = (sacc[nt][1] + RS[r0 * 66 + d1]) * SCL;
            sacc[nt][2] = (sacc[nt][2] + RS[r1 * 66 + d2]) * SCL;
            sacc[nt][3] = (sacc[nt][3] + RS[r1 * 66 + d3]) * SCL;
            tm0 = fmaxf(tm0, fmaxf(sacc[nt][0], sacc[nt][1]));
            tm1 = fmaxf(tm1, fmaxf(sacc[nt][2], sacc[nt][3]));
        }
        tm0 = fmaxf(tm0, __shfl_xor_sync(0xffffffffu, tm0, 1));
        tm0 = fmaxf(tm0, __shfl_xor_sync(0xffffffffu, tm0, 2));
        tm1 = fmaxf(tm1, __shfl_xor_sync(0xffffffffu, tm1, 1));
        tm1 = fmaxf(tm1, __shfl_xor_sync(0xffffffffu, tm1, 2));
        float nm0 = fmaxf(m0, tm0), nm1 = fmaxf(m1, tm1);
        float f0 = ex2(m0 - nm0), f1 = ex2(m1 - nm1);
        float ts0 = 0.f, ts1 = 0.f;
#pragma unroll
        for (int nt = 0; nt < 16; nt++) {
            float p0 = ex2(sacc[nt][0] - nm0);
            float p1 = ex2(sacc[nt][1] - nm0);
            float p2 = ex2(sacc[nt][2] - nm1);
            float p3 = ex2(sacc[nt][3] - nm1);
            ts0 += p0 + p1; ts1 += p2 + p3;
            *(float2*)&Ps[r0 * 132 + nt * 8 + 2 * c] = make_float2(f2tf(p0), f2tf(p1));
            *(float2*)&Ps[r1 * 132 + nt * 8 + 2 * c] = make_float2(f2tf(p2), f2tf(p3));
        }
        ts0 += __shfl_xor_sync(0xffffffffu, ts0, 1);
        ts0 += __shfl_xor_sync(0xffffffffu, ts0, 2);
        ts1 += __shfl_xor_sync(0xffffffffu, ts1, 1);
        ts1 += __shfl_xor_sync(0xffffffffu, ts1, 2);
        l0 = l0 * f0 + ts0;  l1 = l1 * f1 + ts1;
        m0 = nm0;  m1 = nm1;
#pragma unroll
        for (int nt = 0; nt < 8; nt++) {
            oacc[nt][0] *= f0; oacc[nt][1] *= f0;
            oacc[nt][2] *= f1; oacc[nt][3] *= f1;
        }
        if (c == 0) { rowF[r0] = f0; rowF[r1] = f1; }
        __syncthreads();

        // ---- rescale bucket sums ----
        {
            int row = tid >> 1, hf = tid & 1;
            float f = rowF[row];
#pragma unroll
            for (int j = 0; j < 33; j++) {
                int cc = hf * 33 + j;
                if (cc < 65) PrS[row * 66 + cc] *= f;
            }
        }
        __syncthreads();

        // ---- bucket accumulate from Ps ----
        {
            int row = tid >> 1, hf = tid & 1;
            int t = bm + row;
            float lo = 0.f, hi = 0.f;
#pragma unroll
            for (int j = 0; j < 64; j++) {
                int sl = hf * 64 + j;
                float p = Ps[row * 132 + sl];
                int d = bn + sl - t;
                if (d <= -32)      lo += p;
                else if (d >= 32)  hi += p;
                else               PrS[row * 66 + d + 32] += p;
            }
            LH[row * 4 + hf * 2 + 0] = lo;
            LH[row * 4 + hf * 2 + 1] = hi;
        }
        __syncthreads();
        if (tid < 128) {
            PrS[tid * 66 + 0]  += LH[tid * 4 + 0] + LH[tid * 4 + 2];
            PrS[tid * 66 + 64] += LH[tid * 4 + 1] + LH[tid * 4 + 3];
        }

        // ---- O += P @ V over s=128 in four 32-chunks ----
#pragma unroll
        for (int kc2 = 0; kc2 < 128; kc2 += 32) {
            __syncthreads();
            {
                int vrow = tid >> 3, vcol = (tid & 7) * 8;
                float4 v0 = *(const float4*)&Vb[(size_t)(bn + kc2 + vrow) * DKK + vcol];
                float4 v1 = *(const float4*)&Vb[(size_t)(bn + kc2 + vrow) * DKK + vcol + 4];
                v0.x = f2tf(v0.x); v0.y = f2tf(v0.y); v0.z = f2tf(v0.z); v0.w = f2tf(v0.w);
                v1.x = f2tf(v1.x); v1.y = f2tf(v1.y); v1.z = f2tf(v1.z); v1.w = f2tf(v1.w);
                *(float4*)&Vs[vrow * 72 + vcol]     = v0;
                *(float4*)&Vs[vrow * 72 + vcol + 4] = v1;
            }
            __syncthreads();
#pragma unroll
            for (int kk = 0; kk < 4; kk++) {
                int kb = kc2 + kk * 8;
                uint32_t a0 = __float_as_uint(Ps[r0 * 132 + kb + c]);
                uint32_t a1 = __float_as_uint(Ps[r1 * 132 + kb + c]);
                uint32_t a2 = __float_as_uint(Ps[r0 * 132 + kb + c + 4]);
                uint32_t a3 = __float_as_uint(Ps[r1 * 132 + kb + c + 4]);
#pragma unroll
                for (int nt = 0; nt < 8; nt++) {
                    uint32_t b0 = __float_as_uint(Vs[(kk * 8 + c) * 72 + nt * 8 + g]);
                    uint32_t b1 = __float_as_uint(Vs[(kk * 8 + c + 4) * 72 + nt * 8 + g]);
                    mma_tf32(oacc[nt], a0, a1, a2, a3, b0, b1);
                }
            }
        }
        __syncthreads();   // Ps / Ks reusable next tile
    }

    // =============== final epilogue ===============
    {
        float* Es = Ps;   // [65][68]
        for (int i = tid; i < NREL * 64; i += 256) {
            int r = i >> 6, d = i & 63;
            Es[r * 68 + d] = embS[i];
        }
    }
    __syncthreads();

    // relative-value term: oacc += PrS_row . emb_S
    for (int r = 0; r < NREL; r++) {
        float p0 = PrS[r0 * 66 + r];
        float p1 = PrS[r1 * 66 + r];
#pragma unroll
        for (int nt = 0; nt < 8; nt++) {
            float e0 = Ps[r * 68 + nt * 8 + 2 * c];       // Es
            float e1 = Ps[r * 68 + nt * 8 + 2 * c + 1];
            oacc[nt][0] += p0 * e0;  oacc[nt][1] += p0 * e1;
            oacc[nt][2] += p1 * e0;  oacc[nt][3] += p1 * e1;
        }
    }

    const float inv0 = 1.f / l0, inv1 = 1.f / l1;
    const int b = bh >> 4, h = bh & 15;
    float* Hp = g_heads + (size_t)b * TT * DM + h * DKK;
#pragma unroll
    for (int nt = 0; nt < 8; nt++) {
        *(float2*)&Hp[(size_t)(bm + r0) * DM + nt * 8 + 2 * c] =
            make_float2(oacc[nt][0] * inv0, oacc[nt][1] * inv0);
        *(float2*)&Hp[(size_t)(bm + r1) * DM + nt * 8 + 2 * c] =
            make_float2(oacc[nt][2] * inv1, oacc[nt][3] * inv1);
    }
}

// ===========================================================================
// Output GEMM (tf32): C[n, m] = sum_k A[n,k] * Bm[k,m]; 4096x1024x1024.
// ===========================================================================
__global__ __launch_bounds__(256) void out_tf32(const float* __restrict__ A,
                                                const float* __restrict__ Bm,
                                                float* __restrict__ C)
{
    __shared__ float As[128][PADA];
    __shared__ float Bs[32][PADB];

    const int bm = blockIdx.y * 128;
    const int bn = blockIdx.x * 128;
    const int tid = threadIdx.x;

    const int ra  = tid & 127;
    const int kca = (tid >> 7) * 16;
    const int kb  = tid >> 3;
    const int ncb = (tid & 7) * 16;

    const int warp = tid >> 5, lane = tid & 31;
    const int g = lane >> 2, c = lane & 3;
    const int wm = (warp >> 2) * 64;
    const int wn = (warp & 3) * 32;

    float acc[4][4][4];
#pragma unroll
    for (int i = 0; i < 4; i++)
#pragma unroll
        for (int j = 0; j < 4; j++)
#pragma unroll
            for (int e = 0; e < 4; e++) acc[i][j][e] = 0.f;

    float4 arg[4], brg[4];

#define OUT_LOAD(K0)                                                           \
    {                                                                          \
        _Pragma("unroll")                                                      \
        for (int j = 0; j < 4; j++)                                            \
            arg[j] = *(const float4*)&A[(size_t)(bm + ra) * DM + (K0) + kca + 4*j]; \
        _Pragma("unroll")                                                      \
        for (int j = 0; j < 4; j++)                                            \
            brg[j] = *(const float4*)&Bm[(size_t)((K0) + kb) * DM + bn + ncb + 4*j]; \
    }

    OUT_LOAD(0);
    TILE_STORE_AB();
    __syncthreads();
    for (int k0 = 32; k0 < DM; k0 += 32) {
        OUT_LOAD(k0);
        TILE_COMPUTE_44();
        __syncthreads();
        TILE_STORE_AB();
        __syncthreads();
    }
    TILE_COMPUTE_44();

#pragma unroll
    for (int mt = 0; mt < 4; mt++) {
#pragma unroll
        for (int nt = 0; nt < 4; nt++) {
            int t0 = bm + wm + mt * 16 + g;
            int n0 = bn + wn + nt * 8 + c * 2;
            *(float2*)&C[(size_t)t0 * DM + n0] =
                make_float2(acc[mt][nt][0], acc[mt][nt][1]);
            *(float2*)&C[(size_t)(t0 + 8) * DM + n0] =
                make_float2(acc[mt][nt][2], acc[mt][nt][3]);
        }
    }
}

// ---------------------------------------------------------------------------
extern "C" void kernel_launch(void* const* d_in, const int* in_sizes, int n_in,
                              void* d_out, int out_size)
{
    const float* q  = (const float*)d_in[0];
    const float* v  = (const float*)d_in[1];
    const float* WQ = (const float*)d_in[2];
    const float* WK = (const float*)d_in[3];
    const float* WV = (const float*)d_in[4];
    const float* WO = (const float*)d_in[5];
    const float* eQ = (const float*)d_in[6];
    const float* eS = (const float*)d_in[7];
    float* out = (float*)d_out;

    float *qW, *kW, *vW, *hd;
    cudaGetSymbolAddress((void**)&qW, g_qW);
    cudaGetSymbolAddress((void**)&kW, g_kW);
    cudaGetSymbolAddress((void**)&vW, g_vW);
    cudaGetSymbolAddress((void**)&hd, g_heads);

    cudaFuncSetAttribute(attn_fused, cudaFuncAttributeMaxDynamicSharedMemorySize,
                         ATTN_SMEM_BYTES);

    proj3_tf32<<<dim3(8, 32, 3), 256>>>(q, v, WQ, WK, WV);
    attn_fused<<<dim3(8, BH), 256, ATTN_SMEM_BYTES>>>(eQ, eS);
    out_tf32<<<dim3(8, 32), 256>>>(hd, WO, out);
}

// round 13
// speedup vs baseline: 2.7131x; 1.2286x over previous
#include <cuda_runtime.h>
#include <math.h>
#include <stdint.h>

#define TT    1024
#define BB    4
#define HH    16
#define DKK   64
#define DM    1024
#define BH    (BB*HH)      // 64
#define NROWS (BB*TT)      // 4096
#define NREL  65

// ---------------- scratch (device globals; no allocation allowed) ----------
__device__ float g_qW[BH * TT * DKK];            // 16 MB
__device__ float g_kW[BH * TT * DKK];            // 16 MB
__device__ float g_vW[BH * TT * DKK];            // 16 MB
__device__ float g_heads[NROWS * DM];            // 16 MB (tf32-rounded)
__device__ float g_arena[12 * 1024 * 1024];      // 48 MB: Xq, Xv, Bt[4]

#define XQ_OFF   0
#define XV_OFF   (4*1024*1024)
#define BT_OFF   (8*1024*1024)      // + z * 1M floats, z = Q,K,V,O

// ---------------------------------------------------------------------------
// helpers
// ---------------------------------------------------------------------------
__device__ __forceinline__ float f2tf(float x) {
    uint32_t u;
    asm("cvt.rna.tf32.f32 %0, %1;" : "=r"(u) : "f"(x));
    return __uint_as_float(u);
}

__device__ __forceinline__ float ex2(float x) {
    float y;
    asm("ex2.approx.f32 %0, %1;" : "=f"(y) : "f"(x));
    return y;
}

__device__ __forceinline__ void mma_tf32(float c[4],
                                         uint32_t a0, uint32_t a1, uint32_t a2, uint32_t a3,
                                         uint32_t b0, uint32_t b1)
{
    asm volatile(
        "mma.sync.aligned.m16n8k8.row.col.f32.tf32.tf32.f32 "
        "{%0,%1,%2,%3}, {%4,%5,%6,%7}, {%8,%9}, {%0,%1,%2,%3};"
        : "+f"(c[0]), "+f"(c[1]), "+f"(c[2]), "+f"(c[3])
        : "r"(a0), "r"(a1), "r"(a2), "r"(a3), "r"(b0), "r"(b1));
}

__device__ __forceinline__ uint32_t smem_u32(const void* p) {
    return (uint32_t)__cvta_generic_to_shared(p);
}

// ===========================================================================
// prep: round q, v into arena (tf32)
// ===========================================================================
__global__ __launch_bounds__(256) void prep_round(const float* __restrict__ q,
                                                  const float* __restrict__ v)
{
    size_t i = ((size_t)blockIdx.x * 256 + threadIdx.x) * 4;
    float4 a = *(const float4*)&q[i];
    a.x = f2tf(a.x); a.y = f2tf(a.y); a.z = f2tf(a.z); a.w = f2tf(a.w);
    *(float4*)&g_arena[XQ_OFF + i] = a;
    float4 b = *(const float4*)&v[i];
    b.x = f2tf(b.x); b.y = f2tf(b.y); b.z = f2tf(b.z); b.w = f2tf(b.w);
    *(float4*)&g_arena[XV_OFF + i] = b;
}

// ===========================================================================
// prep: transpose + round weights into Bt[n][k] (1024x1024 each)
// z=0..2 : src element (k, n) = W[h=n>>6][m=k][d=n&63]   (W_Q/W_K/W_V)
// z=3    : src element (k, n) = W_O[k*1024 + n]          (W_O flat [(h,d)][m])
// ===========================================================================
__global__ __launch_bounds__(256) void prep_transpose(const float* __restrict__ WQ,
                                                      const float* __restrict__ WK,
                                                      const float* __restrict__ WV,
                                                      const float* __restrict__ WO)
{
    __shared__ float tile[32][33];
    const int z = blockIdx.z;
    const float* src = (z == 0) ? WQ : (z == 1) ? WK : (z == 2) ? WV : WO;
    float* dst = g_arena + BT_OFF + (size_t)z * 1024 * 1024;
    const int k0 = blockIdx.x * 32, n0 = blockIdx.y * 32;
    const int tx = threadIdx.x & 31, ty = threadIdx.x >> 5;

#pragma unroll
    for (int i = 0; i < 32; i += 8) {
        int k = k0 + ty + i, n = n0 + tx;
        float val;
        if (z < 3) val = src[(size_t)(n >> 6) * 65536 + (size_t)k * 64 + (n & 63)];
        else       val = src[(size_t)k * 1024 + n];
        tile[ty + i][tx] = f2tf(val);
    }
    __syncthreads();
#pragma unroll
    for (int i = 0; i < 32; i += 8) {
        int n = n0 + ty + i, k = k0 + tx;
        dst[(size_t)n * 1024 + k] = tile[tx][ty + i];
    }
}

// ===========================================================================
// Dense GEMM (mma.sync tf32, pre-rounded operands, cp.async staging).
// C[m, n] = sum_k A[m][k] * Bt[n][k].  Block tile 128(M) x 256(N), K chunks 32.
// 8 warps as 2(m) x 4(n): warp tile 64 x 64 (mt=4, nt=8).
// Smem rows stride 36 floats (conflict-free fragment reads), 2 buffers.
// mode 1: proj z in {0,1,2}: A = arena X, B = arena Bt[z], scatter to g_{qkv}W
// mode 0: out proj:          A = g_heads, B = arena Bt[3], C = d_out
// ===========================================================================
#define RST  36                       // row stride in floats (144 B)
#define GA_ROWS 128
#define GB_ROWS 256
#define BUF_FLOATS ((GA_ROWS + GB_ROWS) * RST)       // 13824 floats
#define GS_SMEM (2 * BUF_FLOATS * 4)                 // 110592 bytes

__global__ __launch_bounds__(256) void gemm_simt(float* __restrict__ Cout, int mode)
{
    extern __shared__ float sh[];
    const int tid = threadIdx.x;
    const int z = blockIdx.z;

    const float *A, *B;
    if (mode) {
        A = g_arena + ((z == 0) ? XQ_OFF : XV_OFF);
        B = g_arena + BT_OFF + (size_t)z * 1024 * 1024;
    } else {
        A = g_heads;
        B = g_arena + BT_OFF + (size_t)3 * 1024 * 1024;
    }

    const int bm = blockIdx.y * 128;
    const int bn = blockIdx.x * 256;

    float* bufA[2] = { sh, sh + BUF_FLOATS };
    float* bufB[2] = { sh + GA_ROWS * RST, sh + BUF_FLOATS + GA_ROWS * RST };
    const uint32_t sA[2] = { smem_u32(bufA[0]), smem_u32(bufA[1]) };
    const uint32_t sB[2] = { smem_u32(bufB[0]), smem_u32(bufB[1]) };

    const int warp = tid >> 5, lane = tid & 31;
    const int g = lane >> 2, c = lane & 3;
    const int wm = (warp >> 2) * 64;      // 0 or 64
    const int wn = (warp & 3) * 64;       // 0,64,128,192

    float acc[4][8][4];
#pragma unroll
    for (int i = 0; i < 4; i++)
#pragma unroll
        for (int j = 0; j < 8; j++)
#pragma unroll
            for (int e = 0; e < 4; e++) acc[i][j][e] = 0.f;

    // cp.async chunk loader: A rows 128x128B (4/thread), B rows 256x128B (8/thread)
#define GS_LOAD(CH, BUF)                                                       \
    {                                                                          \
        const int k0 = (CH) * 32;                                              \
        _Pragma("unroll")                                                      \
        for (int i = 0; i < 4; i++) {                                          \
            int idx = tid + i * 256;                                           \
            int row = idx >> 3, seg = idx & 7;                                 \
            const float* src = A + (size_t)(bm + row) * 1024 + k0 + seg * 4;   \
            asm volatile("cp.async.cg.shared.global [%0], [%1], 16;"           \
                         :: "r"(sA[BUF] + (uint32_t)(row * 144 + seg * 16)),   \
                            "l"(src));                                         \
        }                                                                      \
        _Pragma("unroll")                                                      \
        for (int i = 0; i < 8; i++) {                                          \
            int idx = tid + i * 256;                                           \
            int row = idx >> 3, seg = idx & 7;                                 \
            const float* src = B + (size_t)(bn + row) * 1024 + k0 + seg * 4;   \
            asm volatile("cp.async.cg.shared.global [%0], [%1], 16;"           \
                         :: "r"(sB[BUF] + (uint32_t)(row * 144 + seg * 16)),   \
                            "l"(src));                                         \
        }                                                                      \
        asm volatile("cp.async.commit_group;");                                \
    }

#define GS_COMPUTE(BUF)                                                        \
    {                                                                          \
        const float* As_ = bufA[BUF];                                          \
        const float* Bs_ = bufB[BUF];                                          \
        _Pragma("unroll")                                                      \
        for (int kk = 0; kk < 4; kk++) {                                       \
            const int kbs = kk * 8;                                            \
            uint32_t af[4][4], bf[8][2];                                       \
            _Pragma("unroll")                                                  \
            for (int mt = 0; mt < 4; mt++) {                                   \
                const int rm = wm + mt * 16;                                   \
                af[mt][0] = __float_as_uint(As_[(rm + g    ) * RST + kbs + c    ]); \
                af[mt][1] = __float_as_uint(As_[(rm + g + 8) * RST + kbs + c    ]); \
                af[mt][2] = __float_as_uint(As_[(rm + g    ) * RST + kbs + c + 4]); \
                af[mt][3] = __float_as_uint(As_[(rm + g + 8) * RST + kbs + c + 4]); \
            }                                                                  \
            _Pragma("unroll")                                                  \
            for (int nt = 0; nt < 8; nt++) {                                   \
                bf[nt][0] = __float_as_uint(Bs_[(wn + nt * 8 + g) * RST + kbs + c    ]); \
                bf[nt][1] = __float_as_uint(Bs_[(wn + nt * 8 + g) * RST + kbs + c + 4]); \
            }                                                                  \
            _Pragma("unroll")                                                  \
            for (int mt = 0; mt < 4; mt++)                                     \
                _Pragma("unroll")                                              \
                for (int nt = 0; nt < 8; nt++)                                 \
                    mma_tf32(acc[mt][nt], af[mt][0], af[mt][1], af[mt][2],     \
                             af[mt][3], bf[nt][0], bf[nt][1]);                 \
        }                                                                      \
    }

    GS_LOAD(0, 0);
    GS_LOAD(1, 1);

    for (int ch = 0; ch < 32; ch++) {
        const int buf = ch & 1;
        if (ch < 31) asm volatile("cp.async.wait_group 1;");
        else         asm volatile("cp.async.wait_group 0;");
        __syncthreads();
        GS_COMPUTE(buf);
        __syncthreads();
        if (ch + 2 < 32) GS_LOAD(ch + 2, buf);
    }

    // epilogue
    if (mode == 0) {
#pragma unroll
        for (int mt = 0; mt < 4; mt++) {
            int r = bm + wm + mt * 16 + g;
#pragma unroll
            for (int nt = 0; nt < 8; nt++) {
                int n0 = bn + wn + nt * 8 + 2 * c;
                *(float2*)&Cout[(size_t)r * DM + n0] =
                    make_float2(acc[mt][nt][0], acc[mt][nt][1]);
                *(float2*)&Cout[(size_t)(r + 8) * DM + n0] =
                    make_float2(acc[mt][nt][2], acc[mt][nt][3]);
            }
        }
    } else {
        float* O = (z == 0) ? g_qW : (z == 1) ? g_kW : g_vW;
        const int h = (bn + wn) >> 6;      // wn multiple of 64 -> fixed head
#pragma unroll
        for (int mt = 0; mt < 4; mt++) {
            int r = bm + wm + mt * 16 + g;
            int b = r >> 10, t = r & 1023;
            size_t base0 = ((size_t)(b * HH + h) * TT + t) * DKK;
            size_t base1 = ((size_t)(b * HH + h) * TT + ((r + 8) & 1023)) * DKK
                         + ((size_t)((r + 8) >> 10) - b) * HH * TT * DKK;
#pragma unroll
            for (int nt = 0; nt < 8; nt++) {
                int d = nt * 8 + 2 * c;
                *(float2*)&O[base0 + d] = make_float2(acc[mt][nt][0], acc[mt][nt][1]);
                *(float2*)&O[base1 + d] = make_float2(acc[mt][nt][2], acc[mt][nt][3]);
            }
        }
    }
}

// ===========================================================================
// Fused flash attention with relative position terms (R9 proven version;
// heads stored tf32-rounded for the out GEMM).
// ===========================================================================
#define SM_AS   0                    // As[128][68]  Q tile tf32
#define SM_KS   8704                 // Ks[32][136]  K chunk (k-major)
#define SM_VS   13056                // Vs[32][72]   V chunk
#define SM_RS   15360                // RS[128][66]  relative-Q bias table
#define SM_PR   23808                // PrS[128][66] bucketed prob sums
#define SM_RF   32256                // rowF[128]    rescale factors
#define SM_E64  32384                // E64[64]      emb_Q row 64
#define SM_LH   32448                // LH[128][4]   lo/hi partials
#define SM_PS   32960                // Ps[128][132] P tile (overlays Et / Es)
#define SM_FTOT 49856
#define ATTN_SMEM_BYTES (SM_FTOT * 4)

__global__ __launch_bounds__(256, 1) void attn_fused(const float* __restrict__ embQ,
                                                     const float* __restrict__ embS)
{
    extern __shared__ float sm[];
    float* As   = sm + SM_AS;    // stride 68
    float* Ks   = sm + SM_KS;    // stride 136
    float* Vs   = sm + SM_VS;    // stride 72
    float* RS   = sm + SM_RS;    // stride 66
    float* PrS  = sm + SM_PR;    // stride 66
    float* rowF = sm + SM_RF;
    float* E64  = sm + SM_E64;
    float* LH   = sm + SM_LH;    // stride 4
    float* Ps   = sm + SM_PS;    // stride 132

    const int bh = blockIdx.y;
    const int bm = blockIdx.x * 128;
    const float* Qb = g_qW + (size_t)bh * TT * DKK;
    const float* Kb = g_kW + (size_t)bh * TT * DKK;
    const float* Vb = g_vW + (size_t)bh * TT * DKK;

    const int tid  = threadIdx.x;
    const int warp = tid >> 5, lane = tid & 31;
    const int g = lane >> 2, c = lane & 3;
    const int r0 = warp * 16 + g;
    const int r1 = r0 + 8;

    // ---------- prologue: load Q tile ----------
#pragma unroll
    for (int rep = 0; rep < 4; rep++) {
        int idx = rep * 2048 + tid * 8;
        int row = idx >> 6, col = idx & 63;
        float4 v0 = *(const float4*)&Qb[(size_t)bm * DKK + idx];
        float4 v1 = *(const float4*)&Qb[(size_t)bm * DKK + idx + 4];
        v0.x = f2tf(v0.x); v0.y = f2tf(v0.y); v0.z = f2tf(v0.z); v0.w = f2tf(v0.w);
        v1.x = f2tf(v1.x); v1.y = f2tf(v1.y); v1.z = f2tf(v1.z); v1.w = f2tf(v1.w);
        *(float4*)&As[row * 68 + col]     = v0;
        *(float4*)&As[row * 68 + col + 4] = v1;
    }
    {
        float* Et = Ps;  // [64][68] transposed emb_Q
        for (int i = tid; i < 4096; i += 256) {
            int k = i & 63, r = i >> 6;
            Et[k * 68 + r] = f2tf(embQ[r * 64 + k]);
        }
        if (tid < 64) E64[tid] = embQ[64 * 64 + tid];
    }
    for (int i = tid; i < 128 * 66; i += 256) PrS[i] = 0.f;
    __syncthreads();

    // ---------- RS = Q_tile @ emb_Q^T ----------
    {
        float* Et = Ps;
        float racc[8][4];
#pragma unroll
        for (int nt = 0; nt < 8; nt++)
#pragma unroll
            for (int e = 0; e < 4; e++) racc[nt][e] = 0.f;
#pragma unroll
        for (int kk = 0; kk < 8; kk++) {
            uint32_t a0 = __float_as_uint(As[r0 * 68 + kk * 8 + c]);
            uint32_t a1 = __float_as_uint(As[r1 * 68 + kk * 8 + c]);
            uint32_t a2 = __float_as_uint(As[r0 * 68 + kk * 8 + c + 4]);
            uint32_t a3 = __float_as_uint(As[r1 * 68 + kk * 8 + c + 4]);
#pragma unroll
            for (int nt = 0; nt < 8; nt++) {
                uint32_t b0 = __float_as_uint(Et[(kk * 8 + c) * 68 + nt * 8 + g]);
                uint32_t b1 = __float_as_uint(Et[(kk * 8 + c + 4) * 68 + nt * 8 + g]);
                mma_tf32(racc[nt], a0, a1, a2, a3, b0, b1);
            }
        }
#pragma unroll
        for (int nt = 0; nt < 8; nt++) {
            *(float2*)&RS[r0 * 66 + nt * 8 + 2 * c] = make_float2(racc[nt][0], racc[nt][1]);
            *(float2*)&RS[r1 * 66 + nt * 8 + 2 * c] = make_float2(racc[nt][2], racc[nt][3]);
        }
    }
    if (tid < 128) {
        float a = 0.f;
#pragma unroll
        for (int k = 0; k < 64; k++) a += As[tid * 68 + k] * E64[k];
        RS[tid * 66 + 64] = a;
    }

    float m0 = -INFINITY, m1 = -INFINITY, l0 = 0.f, l1 = 0.f;
    float oacc[8][4];
#pragma unroll
    for (int nt = 0; nt < 8; nt++)
#pragma unroll
        for (int e = 0; e < 4; e++) oacc[nt][e] = 0.f;

    const float SCL = 0.125f * 1.4426950408889634f;
    const int t0 = bm + r0, t1 = bm + r1;
    __syncthreads();

    // =============== main loop over key tiles ===============
    for (int it = 0; it < 8; it++) {
        const int bn = it * 128;
        float sacc[16][4];
#pragma unroll
        for (int nt = 0; nt < 16; nt++)
#pragma unroll
            for (int e = 0; e < 4; e++) sacc[nt][e] = 0.f;

#pragma unroll
        for (int kc = 0; kc < 64; kc += 32) {
            {
                int s = tid & 127, kh = (tid >> 7) * 16;
                const float* src = &Kb[(size_t)(bn + s) * DKK + kc + kh];
#pragma unroll
                for (int j = 0; j < 4; j++) {
                    float4 v = *(const float4*)&src[4 * j];
                    Ks[(kh + 4 * j + 0) * 136 + s] = f2tf(v.x);
                    Ks[(kh + 4 * j + 1) * 136 + s] = f2tf(v.y);
                    Ks[(kh + 4 * j + 2) * 136 + s] = f2tf(v.z);
                    Ks[(kh + 4 * j + 3) * 136 + s] = f2tf(v.w);
                }
            }
            __syncthreads();
#pragma unroll
            for (int kk = 0; kk < 4; kk++) {
                int kb = kc + kk * 8;
                uint32_t a0 = __float_as_uint(As[r0 * 68 + kb + c]);
                uint32_t a1 = __float_as_uint(As[r1 * 68 + kb + c]);
                uint32_t a2 = __float_as_uint(As[r0 * 68 + kb + c + 4]);
                uint32_t a3 = __float_as_uint(As[r1 * 68 + kb + c + 4]);
#pragma unroll
                for (int nt = 0; nt < 16; nt++) {
                    uint32_t b0 = __float_as_uint(Ks[(kk * 8 + c) * 136 + nt * 8 + g]);
                    uint32_t b1 = __float_as_uint(Ks[(kk * 8 + c + 4) * 136 + nt * 8 + g]);
                    mma_tf32(sacc[nt], a0, a1, a2, a3, b0, b1);
                }
            }
            __syncthreads();
        }

        float tm0 = -INFINITY, tm1 = -INFINITY;
#pragma unroll
        for (int nt = 0; nt < 16; nt++) {
            int s0 = bn + nt * 8 + 2 * c;
            int d0 = min(max(s0 - t0, -32), 32) + 32;
            int d1 = min(max(s0 + 1 - t0, -32), 32) + 32;
            int d2 = min(max(s0 - t1, -32), 32) + 32;
            int d3 = min(max(s0 + 1 - t1, -32), 32) + 32;
            sacc[nt][0] = (sacc[nt][0] + RS[r0 * 66 + d0]) * SCL;
            sacc[nt][1] = (sacc[nt][1] + RS[r0 * 66 + d1]) * SCL;
            sacc[nt][2] = (sacc[nt][2] + RS[r1 * 66 + d2]) * SCL;
            sacc[nt][3] = (sacc[nt][3] + RS[r1 * 66 + d3]) * SCL;
            tm0 = fmaxf(tm0, fmaxf(sacc[nt][0], sacc[nt][1]));
            tm1 = fmaxf(tm1, fmaxf(sacc[nt][2], sacc[nt][3]));
        }
        tm0 = fmaxf(tm0, __shfl_xor_sync(0xffffffffu, tm0, 1));
        tm0 = fmaxf(tm0, __shfl_xor_sync(0xffffffffu, tm0, 2));
        tm1 = fmaxf(tm1, __shfl_xor_sync(0xffffffffu, tm1, 1));
        tm1 = fmaxf(tm1, __shfl_xor_sync(0xffffffffu, tm1, 2));
        float nm0 = fmaxf(m0, tm0), nm1 = fmaxf(m1, tm1);
        float f0 = ex2(m0 - nm0), f1 = ex2(m1 - nm1);
        float ts0 = 0.f, ts1 = 0.f;
#pragma unroll
        for (int nt = 0; nt < 16; nt++) {
            float p0 = ex2(sacc[nt][0] - nm0);
            float p1 = ex2(sacc[nt][1] - nm0);
            float p2 = ex2(sacc[nt][2] - nm1);
            float p3 = ex2(sacc[nt][3] - nm1);
            ts0 += p0 + p1; ts1 += p2 + p3;
            *(float2*)&Ps[r0 * 132 + nt * 8 + 2 * c] = make_float2(f2tf(p0), f2tf(p1));
            *(float2*)&Ps[r1 * 132 + nt * 8 + 2 * c] = make_float2(f2tf(p2), f2tf(p3));
        }
        ts0 += __shfl_xor_sync(0xffffffffu, ts0, 1);
        ts0 += __shfl_xor_sync(0xffffffffu, ts0, 2);
        ts1 += __shfl_xor_sync(0xffffffffu, ts1, 1);
        ts1 += __shfl_xor_sync(0xffffffffu, ts1, 2);
        l0 = l0 * f0 + ts0;  l1 = l1 * f1 + ts1;
        m0 = nm0;  m1 = nm1;
#pragma unroll
        for (int nt = 0; nt < 8; nt++) {
            oacc[nt][0] *= f0; oacc[nt][1] *= f0;
            oacc[nt][2] *= f1; oacc[nt][3] *= f1;
        }
        if (c == 0) { rowF[r0] = f0; rowF[r1] = f1; }
        __syncthreads();

        {
            int row = tid >> 1, hf = tid & 1;
            float f = rowF[row];
#pragma unroll
            for (int j = 0; j < 33; j++) {
                int cc = hf * 33 + j;
                if (cc < 65) PrS[row * 66 + cc] *= f;
            }
        }
        __syncthreads();

        {
            int row = tid >> 1, hf = tid & 1;
            int t = bm + row;
            float lo = 0.f, hi = 0.f;
#pragma unroll
            for (int j = 0; j < 64; j++) {
                int sl = hf * 64 + j;
                float p = Ps[row * 132 + sl];
                int d = bn + sl - t;
                if (d <= -32)      lo += p;
                else if (d >= 32)  hi += p;
                else               PrS[row * 66 + d + 32] += p;
            }
            LH[row * 4 + hf * 2 + 0] = lo;
            LH[row * 4 + hf * 2 + 1] = hi;
        }
        __syncthreads();
        if (tid < 128) {
            PrS[tid * 66 + 0]  += LH[tid * 4 + 0] + LH[tid * 4 + 2];
            PrS[tid * 66 + 64] += LH[tid * 4 + 1] + LH[tid * 4 + 3];
        }

#pragma unroll
        for (int kc2 = 0; kc2 < 128; kc2 += 32) {
            __syncthreads();
            {
                int vrow = tid >> 3, vcol = (tid & 7) * 8;
                float4 v0 = *(const float4*)&Vb[(size_t)(bn + kc2 + vrow) * DKK + vcol];
                float4 v1 = *(const float4*)&Vb[(size_t)(bn + kc2 + vrow) * DKK + vcol + 4];
                v0.x = f2tf(v0.x); v0.y = f2tf(v0.y); v0.z = f2tf(v0.z); v0.w = f2tf(v0.w);
                v1.x = f2tf(v1.x); v1.y = f2tf(v1.y); v1.z = f2tf(v1.z); v1.w = f2tf(v1.w);
                *(float4*)&Vs[vrow * 72 + vcol]     = v0;
                *(float4*)&Vs[vrow * 72 + vcol + 4] = v1;
            }
            __syncthreads();
#pragma unroll
            for (int kk = 0; kk < 4; kk++) {
                int kb = kc2 + kk * 8;
                uint32_t a0 = __float_as_uint(Ps[r0 * 132 + kb + c]);
                uint32_t a1 = __float_as_uint(Ps[r1 * 132 + kb + c]);
                uint32_t a2 = __float_as_uint(Ps[r0 * 132 + kb + c + 4]);
                uint32_t a3 = __float_as_uint(Ps[r1 * 132 + kb + c + 4]);
#pragma unroll
                for (int nt = 0; nt < 8; nt++) {
                    uint32_t b0 = __float_as_uint(Vs[(kk * 8 + c) * 72 + nt * 8 + g]);
                    uint32_t b1 = __float_as_uint(Vs[(kk * 8 + c + 4) * 72 + nt * 8 + g]);
                    mma_tf32(oacc[nt], a0, a1, a2, a3, b0, b1);
                }
            }
        }
        __syncthreads();
    }

    // =============== final epilogue ===============
    {
        float* Es = Ps;   // [65][68]
        for (int i = tid; i < NREL * 64; i += 256) {
            int r = i >> 6, d = i & 63;
            Es[r * 68 + d] = embS[i];
        }
    }
    __syncthreads();

    for (int r = 0; r < NREL; r++) {
        float p0 = PrS[r0 * 66 + r];
        float p1 = PrS[r1 * 66 + r];
#pragma unroll
        for (int nt = 0; nt < 8; nt++) {
            float e0 = Ps[r * 68 + nt * 8 + 2 * c];
            float e1 = Ps[r * 68 + nt * 8 + 2 * c + 1];
            oacc[nt][0] += p0 * e0;  oacc[nt][1] += p0 * e1;
            oacc[nt][2] += p1 * e0;  oacc[nt][3] += p1 * e1;
        }
    }

    const float inv0 = 1.f / l0, inv1 = 1.f / l1;
    const int b = bh >> 4, h = bh & 15;
    float* Hp = g_heads + (size_t)b * TT * DM + h * DKK;
#pragma unroll
    for (int nt = 0; nt < 8; nt++) {
        *(float2*)&Hp[(size_t)(bm + r0) * DM + nt * 8 + 2 * c] =
            make_float2(f2tf(oacc[nt][0] * inv0), f2tf(oacc[nt][1] * inv0));
        *(float2*)&Hp[(size_t)(bm + r1) * DM + nt * 8 + 2 * c] =
            make_float2(f2tf(oacc[nt][2] * inv1), f2tf(oacc[nt][3] * inv1));
    }
}

// ---------------------------------------------------------------------------
extern "C" void kernel_launch(void* const* d_in, const int* in_sizes, int n_in,
                              void* d_out, int out_size)
{
    const float* q  = (const float*)d_in[0];
    const float* v  = (const float*)d_in[1];
    const float* WQ = (const float*)d_in[2];
    const float* WK = (const float*)d_in[3];
    const float* WV = (const float*)d_in[4];
    const float* WO = (const float*)d_in[5];
    const float* eQ = (const float*)d_in[6];
    const float* eS = (const float*)d_in[7];
    float* out = (float*)d_out;

    cudaFuncSetAttribute(attn_fused, cudaFuncAttributeMaxDynamicSharedMemorySize,
                         ATTN_SMEM_BYTES);
    cudaFuncSetAttribute(gemm_simt, cudaFuncAttributeMaxDynamicSharedMemorySize,
                         GS_SMEM);

    prep_round<<<4096, 256>>>(q, v);
    prep_transpose<<<dim3(32, 32, 4), 256>>>(WQ, WK, WV, WO);
    gemm_simt<<<dim3(4, 32, 3), 256, GS_SMEM>>>(nullptr, 1);   // Q,K,V projections
    attn_fused<<<dim3(8, BH), 256, ATTN_SMEM_BYTES>>>(eQ, eS);
    gemm_simt<<<dim3(4, 32, 1), 256, GS_SMEM>>>(out, 0);       // output projection
}

// round 14
// speedup vs baseline: 2.9733x; 1.0959x over previous
#include <cuda_runtime.h>
#include <math.h>
#include <stdint.h>

#define TT    1024
#define BB    4
#define HH    16
#define DKK   64
#define DM    1024
#define BH    (BB*HH)      // 64
#define NROWS (BB*TT)      // 4096
#define NREL  65

// ---------------- scratch (device globals; no allocation allowed) ----------
__device__ float g_qW[BH * TT * DKK];            // 16 MB
__device__ float g_kW[BH * TT * DKK];            // 16 MB
__device__ float g_vW[BH * TT * DKK];            // 16 MB
__device__ float g_heads[NROWS * DM];            // 16 MB (tf32-rounded)
__device__ float g_arena[12 * 1024 * 1024];      // 48 MB: Xq, Xv, Bt[4]

#define XQ_OFF   0
#define XV_OFF   (4*1024*1024)
#define BT_OFF   (8*1024*1024)      // + z * 1M floats, z = Q,K,V,O

// ---------------------------------------------------------------------------
// helpers
// ---------------------------------------------------------------------------
__device__ __forceinline__ float f2tf(float x) {
    uint32_t u;
    asm("cvt.rna.tf32.f32 %0, %1;" : "=r"(u) : "f"(x));
    return __uint_as_float(u);
}

__device__ __forceinline__ float ex2(float x) {
    float y;
    asm("ex2.approx.f32 %0, %1;" : "=f"(y) : "f"(x));
    return y;
}

__device__ __forceinline__ void mma_tf32(float c[4],
                                         uint32_t a0, uint32_t a1, uint32_t a2, uint32_t a3,
                                         uint32_t b0, uint32_t b1)
{
    asm volatile(
        "mma.sync.aligned.m16n8k8.row.col.f32.tf32.tf32.f32 "
        "{%0,%1,%2,%3}, {%4,%5,%6,%7}, {%8,%9}, {%0,%1,%2,%3};"
        : "+f"(c[0]), "+f"(c[1]), "+f"(c[2]), "+f"(c[3])
        : "r"(a0), "r"(a1), "r"(a2), "r"(a3), "r"(b0), "r"(b1));
}

__device__ __forceinline__ uint32_t smem_u32(const void* p) {
    return (uint32_t)__cvta_generic_to_shared(p);
}

// ===========================================================================
// prep: round q, v into arena (tf32)
// ===========================================================================
__global__ __launch_bounds__(256) void prep_round(const float* __restrict__ q,
                                                  const float* __restrict__ v)
{
    size_t i = ((size_t)blockIdx.x * 256 + threadIdx.x) * 4;
    float4 a = *(const float4*)&q[i];
    a.x = f2tf(a.x); a.y = f2tf(a.y); a.z = f2tf(a.z); a.w = f2tf(a.w);
    *(float4*)&g_arena[XQ_OFF + i] = a;
    float4 b = *(const float4*)&v[i];
    b.x = f2tf(b.x); b.y = f2tf(b.y); b.z = f2tf(b.z); b.w = f2tf(b.w);
    *(float4*)&g_arena[XV_OFF + i] = b;
}

// ===========================================================================
// prep: transpose + round weights into Bt[n][k] (1024x1024 each)
// ===========================================================================
__global__ __launch_bounds__(256) void prep_transpose(const float* __restrict__ WQ,
                                                      const float* __restrict__ WK,
                                                      const float* __restrict__ WV,
                                                      const float* __restrict__ WO)
{
    __shared__ float tile[32][33];
    const int z = blockIdx.z;
    const float* src = (z == 0) ? WQ : (z == 1) ? WK : (z == 2) ? WV : WO;
    float* dst = g_arena + BT_OFF + (size_t)z * 1024 * 1024;
    const int k0 = blockIdx.x * 32, n0 = blockIdx.y * 32;
    const int tx = threadIdx.x & 31, ty = threadIdx.x >> 5;

#pragma unroll
    for (int i = 0; i < 32; i += 8) {
        int k = k0 + ty + i, n = n0 + tx;
        float val;
        if (z < 3) val = src[(size_t)(n >> 6) * 65536 + (size_t)k * 64 + (n & 63)];
        else       val = src[(size_t)k * 1024 + n];
        tile[ty + i][tx] = f2tf(val);
    }
    __syncthreads();
#pragma unroll
    for (int i = 0; i < 32; i += 8) {
        int n = n0 + ty + i, k = k0 + tx;
        dst[(size_t)n * 1024 + k] = tile[tx][ty + i];
    }
}

// ===========================================================================
// Dense GEMM (mma.sync tf32, pre-rounded operands, cp.async staging).
// ===========================================================================
#define RST  36
#define GA_ROWS 128
#define GB_ROWS 256
#define BUF_FLOATS ((GA_ROWS + GB_ROWS) * RST)
#define GS_SMEM (2 * BUF_FLOATS * 4)

__global__ __launch_bounds__(256) void gemm_simt(float* __restrict__ Cout, int mode)
{
    extern __shared__ float sh[];
    const int tid = threadIdx.x;
    const int z = blockIdx.z;

    const float *A, *B;
    if (mode) {
        A = g_arena + ((z == 0) ? XQ_OFF : XV_OFF);
        B = g_arena + BT_OFF + (size_t)z * 1024 * 1024;
    } else {
        A = g_heads;
        B = g_arena + BT_OFF + (size_t)3 * 1024 * 1024;
    }

    const int bm = blockIdx.y * 128;
    const int bn = blockIdx.x * 256;

    float* bufA[2] = { sh, sh + BUF_FLOATS };
    float* bufB[2] = { sh + GA_ROWS * RST, sh + BUF_FLOATS + GA_ROWS * RST };
    const uint32_t sA[2] = { smem_u32(bufA[0]), smem_u32(bufA[1]) };
    const uint32_t sB[2] = { smem_u32(bufB[0]), smem_u32(bufB[1]) };

    const int warp = tid >> 5, lane = tid & 31;
    const int g = lane >> 2, c = lane & 3;
    const int wm = (warp >> 2) * 64;
    const int wn = (warp & 3) * 64;

    float acc[4][8][4];
#pragma unroll
    for (int i = 0; i < 4; i++)
#pragma unroll
        for (int j = 0; j < 8; j++)
#pragma unroll
            for (int e = 0; e < 4; e++) acc[i][j][e] = 0.f;

#define GS_LOAD(CH, BUF)                                                       \
    {                                                                          \
        const int k0 = (CH) * 32;                                              \
        _Pragma("unroll")                                                      \
        for (int i = 0; i < 4; i++) {                                          \
            int idx = tid + i * 256;                                           \
            int row = idx >> 3, seg = idx & 7;                                 \
            const float* src = A + (size_t)(bm + row) * 1024 + k0 + seg * 4;   \
            asm volatile("cp.async.cg.shared.global [%0], [%1], 16;"           \
                         :: "r"(sA[BUF] + (uint32_t)(row * 144 + seg * 16)),   \
                            "l"(src));                                         \
        }                                                                      \
        _Pragma("unroll")                                                      \
        for (int i = 0; i < 8; i++) {                                          \
            int idx = tid + i * 256;                                           \
            int row = idx >> 3, seg = idx & 7;                                 \
            const float* src = B + (size_t)(bn + row) * 1024 + k0 + seg * 4;   \
            asm volatile("cp.async.cg.shared.global [%0], [%1], 16;"           \
                         :: "r"(sB[BUF] + (uint32_t)(row * 144 + seg * 16)),   \
                            "l"(src));                                         \
        }                                                                      \
        asm volatile("cp.async.commit_group;");                                \
    }

#define GS_COMPUTE(BUF)                                                        \
    {                                                                          \
        const float* As_ = bufA[BUF];                                          \
        const float* Bs_ = bufB[BUF];                                          \
        _Pragma("unroll")                                                      \
        for (int kk = 0; kk < 4; kk++) {                                       \
            const int kbs = kk * 8;                                            \
            uint32_t af[4][4], bf[8][2];                                       \
            _Pragma("unroll")                                                  \
            for (int mt = 0; mt < 4; mt++) {                                   \
                const int rm = wm + mt * 16;                                   \
                af[mt][0] = __float_as_uint(As_[(rm + g    ) * RST + kbs + c    ]); \
                af[mt][1] = __float_as_uint(As_[(rm + g + 8) * RST + kbs + c    ]); \
                af[mt][2] = __float_as_uint(As_[(rm + g    ) * RST + kbs + c + 4]); \
                af[mt][3] = __float_as_uint(As_[(rm + g + 8) * RST + kbs + c + 4]); \
            }                                                                  \
            _Pragma("unroll")                                                  \
            for (int nt = 0; nt < 8; nt++) {                                   \
                bf[nt][0] = __float_as_uint(Bs_[(wn + nt * 8 + g) * RST + kbs + c    ]); \
                bf[nt][1] = __float_as_uint(Bs_[(wn + nt * 8 + g) * RST + kbs + c + 4]); \
            }                                                                  \
            _Pragma("unroll")                                                  \
            for (int mt = 0; mt < 4; mt++)                                     \
                _Pragma("unroll")                                              \
                for (int nt = 0; nt < 8; nt++)                                 \
                    mma_tf32(acc[mt][nt], af[mt][0], af[mt][1], af[mt][2],     \
                             af[mt][3], bf[nt][0], bf[nt][1]);                 \
        }                                                                      \
    }

    GS_LOAD(0, 0);
    GS_LOAD(1, 1);

    for (int ch = 0; ch < 32; ch++) {
        const int buf = ch & 1;
        if (ch < 31) asm volatile("cp.async.wait_group 1;");
        else         asm volatile("cp.async.wait_group 0;");
        __syncthreads();
        GS_COMPUTE(buf);
        __syncthreads();
        if (ch + 2 < 32) GS_LOAD(ch + 2, buf);
    }

    if (mode == 0) {
#pragma unroll
        for (int mt = 0; mt < 4; mt++) {
            int r = bm + wm + mt * 16 + g;
#pragma unroll
            for (int nt = 0; nt < 8; nt++) {
                int n0 = bn + wn + nt * 8 + 2 * c;
                *(float2*)&Cout[(size_t)r * DM + n0] =
                    make_float2(acc[mt][nt][0], acc[mt][nt][1]);
                *(float2*)&Cout[(size_t)(r + 8) * DM + n0] =
                    make_float2(acc[mt][nt][2], acc[mt][nt][3]);
            }
        }
    } else {
        float* O = (z == 0) ? g_qW : (z == 1) ? g_kW : g_vW;
        const int h = (bn + wn) >> 6;
#pragma unroll
        for (int mt = 0; mt < 4; mt++) {
            int r = bm + wm + mt * 16 + g;
            int b = r >> 10, t = r & 1023;
            size_t base0 = ((size_t)(b * HH + h) * TT + t) * DKK;
            size_t base1 = ((size_t)(b * HH + h) * TT + ((r + 8) & 1023)) * DKK
                         + ((size_t)((r + 8) >> 10) - b) * HH * TT * DKK;
#pragma unroll
            for (int nt = 0; nt < 8; nt++) {
                int d = nt * 8 + 2 * c;
                *(float2*)&O[base0 + d] = make_float2(acc[mt][nt][0], acc[mt][nt][1]);
                *(float2*)&O[base1 + d] = make_float2(acc[mt][nt][2], acc[mt][nt][3]);
            }
        }
    }
}

// ===========================================================================
// Fused flash attention with relative position terms.
// New bucket scheme: middle buckets written ONCE as absolute base-2 scores
// (converted to probs at the end); lo/hi are 2 online scalars per row whose
// per-tile contribution is the already-computed tile row-sum except on the
// <=3 diagonal-band tiles, which run a short register scan.
// ===========================================================================
#define SM_AS   0                    // As[128][68]  Q tile tf32
#define SM_KS   8704                 // Ks[32][136]  K chunk (k-major)
#define SM_VS   13056                // Vs[32][72]   V chunk
#define SM_RS   15360                // RS[128][66]  relative-Q bias table
#define SM_PR   23808                // PrS[128][64] middle-bucket s2 scores
#define SM_LO   32000                // rowLO[128]
#define SM_HI   32128                // rowHI[128]
#define SM_M    32256                // rowM[128]
#define SM_PS   32384                // Ps[128][132] P tile (overlays Et / Es)
#define SM_E64  49280                // E64[64]
#define SM_FTOT 49344
#define ATTN_SMEM_BYTES (SM_FTOT * 4)

__global__ __launch_bounds__(256, 1) void attn_fused(const float* __restrict__ embQ,
                                                     const float* __restrict__ embS)
{
    extern __shared__ float sm[];
    float* As    = sm + SM_AS;    // stride 68
    float* Ks    = sm + SM_KS;    // stride 136
    float* Vs    = sm + SM_VS;    // stride 72
    float* RS    = sm + SM_RS;    // stride 66
    float* PrS   = sm + SM_PR;    // stride 64
    float* rowLO = sm + SM_LO;
    float* rowHI = sm + SM_HI;
    float* rowM  = sm + SM_M;
    float* Ps    = sm + SM_PS;    // stride 132
    float* E64   = sm + SM_E64;

    const int bh = blockIdx.y;
    const int bm = blockIdx.x * 128;
    const float* Qb = g_qW + (size_t)bh * TT * DKK;
    const float* Kb = g_kW + (size_t)bh * TT * DKK;
    const float* Vb = g_vW + (size_t)bh * TT * DKK;

    const int tid  = threadIdx.x;
    const int warp = tid >> 5, lane = tid & 31;
    const int g = lane >> 2, c = lane & 3;
    const int r0 = warp * 16 + g;
    const int r1 = r0 + 8;

    // ---------- prologue: load Q tile ----------
#pragma unroll
    for (int rep = 0; rep < 4; rep++) {
        int idx = rep * 2048 + tid * 8;
        int row = idx >> 6, col = idx & 63;
        float4 v0 = *(const float4*)&Qb[(size_t)bm * DKK + idx];
        float4 v1 = *(const float4*)&Qb[(size_t)bm * DKK + idx + 4];
        v0.x = f2tf(v0.x); v0.y = f2tf(v0.y); v0.z = f2tf(v0.z); v0.w = f2tf(v0.w);
        v1.x = f2tf(v1.x); v1.y = f2tf(v1.y); v1.z = f2tf(v1.z); v1.w = f2tf(v1.w);
        *(float4*)&As[row * 68 + col]     = v0;
        *(float4*)&As[row * 68 + col + 4] = v1;
    }
    {
        float* Et = Ps;  // [64][68] transposed emb_Q
        for (int i = tid; i < 4096; i += 256) {
            int k = i & 63, r = i >> 6;
            Et[k * 68 + r] = f2tf(embQ[r * 64 + k]);
        }
        if (tid < 64) E64[tid] = embQ[64 * 64 + tid];
    }
    for (int i = tid; i < 128 * 64; i += 256) PrS[i] = -1e30f;
    if (tid < 128) { rowLO[tid] = 0.f; rowHI[tid] = 0.f; }
    __syncthreads();

    // ---------- RS = Q_tile @ emb_Q^T ----------
    {
        float* Et = Ps;
        float racc[8][4];
#pragma unroll
        for (int nt = 0; nt < 8; nt++)
#pragma unroll
            for (int e = 0; e < 4; e++) racc[nt][e] = 0.f;
#pragma unroll
        for (int kk = 0; kk < 8; kk++) {
            uint32_t a0 = __float_as_uint(As[r0 * 68 + kk * 8 + c]);
            uint32_t a1 = __float_as_uint(As[r1 * 68 + kk * 8 + c]);
            uint32_t a2 = __float_as_uint(As[r0 * 68 + kk * 8 + c + 4]);
            uint32_t a3 = __float_as_uint(As[r1 * 68 + kk * 8 + c + 4]);
#pragma unroll
            for (int nt = 0; nt < 8; nt++) {
                uint32_t b0 = __float_as_uint(Et[(kk * 8 + c) * 68 + nt * 8 + g]);
                uint32_t b1 = __float_as_uint(Et[(kk * 8 + c + 4) * 68 + nt * 8 + g]);
                mma_tf32(racc[nt], a0, a1, a2, a3, b0, b1);
            }
        }
#pragma unroll
        for (int nt = 0; nt < 8; nt++) {
            *(float2*)&RS[r0 * 66 + nt * 8 + 2 * c] = make_float2(racc[nt][0], racc[nt][1]);
            *(float2*)&RS[r1 * 66 + nt * 8 + 2 * c] = make_float2(racc[nt][2], racc[nt][3]);
        }
    }
    if (tid < 128) {
        float a = 0.f;
#pragma unroll
        for (int k = 0; k < 64; k++) a += As[tid * 68 + k] * E64[k];
        RS[tid * 66 + 64] = a;
    }

    float m0 = -INFINITY, m1 = -INFINITY, l0 = 0.f, l1 = 0.f;
    float oacc[8][4];
#pragma unroll
    for (int nt = 0; nt < 8; nt++)
#pragma unroll
        for (int e = 0; e < 4; e++) oacc[nt][e] = 0.f;

    const float SCL = 0.125f * 1.4426950408889634f;
    const int t0 = bm + r0, t1 = bm + r1;
    __syncthreads();

    // =============== main loop over key tiles ===============
    for (int it = 0; it < 8; it++) {
        const int bn = it * 128;
        float sacc[16][4];
#pragma unroll
        for (int nt = 0; nt < 16; nt++)
#pragma unroll
            for (int e = 0; e < 4; e++) sacc[nt][e] = 0.f;

        // ---- S = Q K^T ----
#pragma unroll
        for (int kc = 0; kc < 64; kc += 32) {
            {
                int s = tid & 127, kh = (tid >> 7) * 16;
                const float* src = &Kb[(size_t)(bn + s) * DKK + kc + kh];
#pragma unroll
                for (int j = 0; j < 4; j++) {
                    float4 v = *(const float4*)&src[4 * j];
                    Ks[(kh + 4 * j + 0) * 136 + s] = f2tf(v.x);
                    Ks[(kh + 4 * j + 1) * 136 + s] = f2tf(v.y);
                    Ks[(kh + 4 * j + 2) * 136 + s] = f2tf(v.z);
                    Ks[(kh + 4 * j + 3) * 136 + s] = f2tf(v.w);
                }
            }
            __syncthreads();
#pragma unroll
            for (int kk = 0; kk < 4; kk++) {
                int kb = kc + kk * 8;
                uint32_t a0 = __float_as_uint(As[r0 * 68 + kb + c]);
                uint32_t a1 = __float_as_uint(As[r1 * 68 + kb + c]);
                uint32_t a2 = __float_as_uint(As[r0 * 68 + kb + c + 4]);
                uint32_t a3 = __float_as_uint(As[r1 * 68 + kb + c + 4]);
#pragma unroll
                for (int nt = 0; nt < 16; nt++) {
                    uint32_t b0 = __float_as_uint(Ks[(kk * 8 + c) * 136 + nt * 8 + g]);
                    uint32_t b1 = __float_as_uint(Ks[(kk * 8 + c + 4) * 136 + nt * 8 + g]);
                    mma_tf32(sacc[nt], a0, a1, a2, a3, b0, b1);
                }
            }
            __syncthreads();
        }

        // ---- pass 1: bias + scale -> s2 scores (base-2), tile max ----
        float tm0 = -INFINITY, tm1 = -INFINITY;
#pragma unroll
        for (int nt = 0; nt < 16; nt++) {
            int s0 = bn + nt * 8 + 2 * c;
            int d0 = min(max(s0 - t0, -32), 32) + 32;
            int d1 = min(max(s0 + 1 - t0, -32), 32) + 32;
            int d2 = min(max(s0 - t1, -32), 32) + 32;
            int d3 = min(max(s0 + 1 - t1, -32), 32) + 32;
            sacc[nt][0] = (sacc[nt][0] + RS[r0 * 66 + d0]) * SCL;
            sacc[nt][1] = (sacc[nt][1] + RS[r0 * 66 + d1]) * SCL;
            sacc[nt][2] = (sacc[nt][2] + RS[r1 * 66 + d2]) * SCL;
            sacc[nt][3] = (sacc[nt][3] + RS[r1 * 66 + d3]) * SCL;
            tm0 = fmaxf(tm0, fmaxf(sacc[nt][0], sacc[nt][1]));
            tm1 = fmaxf(tm1, fmaxf(sacc[nt][2], sacc[nt][3]));
        }
        tm0 = fmaxf(tm0, __shfl_xor_sync(0xffffffffu, tm0, 1));
        tm0 = fmaxf(tm0, __shfl_xor_sync(0xffffffffu, tm0, 2));
        tm1 = fmaxf(tm1, __shfl_xor_sync(0xffffffffu, tm1, 1));
        tm1 = fmaxf(tm1, __shfl_xor_sync(0xffffffffu, tm1, 2));
        float nm0 = fmaxf(m0, tm0), nm1 = fmaxf(m1, tm1);
        float f0 = ex2(m0 - nm0), f1 = ex2(m1 - nm1);

        // ---- pass 2: probs, tile row-sums, Ps stores ----
        float ts0 = 0.f, ts1 = 0.f;
#pragma unroll
        for (int nt = 0; nt < 16; nt++) {
            float p0 = ex2(sacc[nt][0] - nm0);
            float p1 = ex2(sacc[nt][1] - nm0);
            float p2 = ex2(sacc[nt][2] - nm1);
            float p3 = ex2(sacc[nt][3] - nm1);
            ts0 += p0 + p1; ts1 += p2 + p3;
            *(float2*)&Ps[r0 * 132 + nt * 8 + 2 * c] = make_float2(f2tf(p0), f2tf(p1));
            *(float2*)&Ps[r1 * 132 + nt * 8 + 2 * c] = make_float2(f2tf(p2), f2tf(p3));
        }
        ts0 += __shfl_xor_sync(0xffffffffu, ts0, 1);
        ts0 += __shfl_xor_sync(0xffffffffu, ts0, 2);
        ts1 += __shfl_xor_sync(0xffffffffu, ts1, 1);
        ts1 += __shfl_xor_sync(0xffffffffu, ts1, 2);
        l0 = l0 * f0 + ts0;  l1 = l1 * f1 + ts1;
        m0 = nm0;  m1 = nm1;
#pragma unroll
        for (int nt = 0; nt < 8; nt++) {
            oacc[nt][0] *= f0; oacc[nt][1] *= f0;
            oacc[nt][2] *= f1; oacc[nt][3] *= f1;
        }

        // ---- bucket step (cheap path for off-diagonal tiles) ----
        {
            const bool alllo0 = (t0 >= bn + 159), allhi0 = (t0 <= bn - 32);
            const bool alllo1 = (t1 >= bn + 159), allhi1 = (t1 <= bn - 32);
            const bool sc0 = !(alllo0 || allhi0);
            const bool sc1 = !(alllo1 || allhi1);
            float plo0 = 0.f, phi0 = 0.f, plo1 = 0.f, phi1 = 0.f;
            if (sc0) {
#pragma unroll
                for (int nt = 0; nt < 16; nt++) {
#pragma unroll
                    for (int e = 0; e < 2; e++) {
                        int d = bn + nt * 8 + 2 * c + e - t0;
                        float s2 = sacc[nt][e];
                        if (d <= -32)      plo0 += ex2(s2 - nm0);
                        else if (d >= 32)  phi0 += ex2(s2 - nm0);
                        else               PrS[r0 * 64 + d + 32] = s2;
                    }
                }
            }
            if (sc1) {
#pragma unroll
                for (int nt = 0; nt < 16; nt++) {
#pragma unroll
                    for (int e = 0; e < 2; e++) {
                        int d = bn + nt * 8 + 2 * c + e - t1;
                        float s2 = sacc[nt][e + 2];
                        if (d <= -32)      plo1 += ex2(s2 - nm1);
                        else if (d >= 32)  phi1 += ex2(s2 - nm1);
                        else               PrS[r1 * 64 + d + 32] = s2;
                    }
                }
            }
            plo0 += __shfl_xor_sync(0xffffffffu, plo0, 1);
            plo0 += __shfl_xor_sync(0xffffffffu, plo0, 2);
            phi0 += __shfl_xor_sync(0xffffffffu, phi0, 1);
            phi0 += __shfl_xor_sync(0xffffffffu, phi0, 2);
            plo1 += __shfl_xor_sync(0xffffffffu, plo1, 1);
            plo1 += __shfl_xor_sync(0xffffffffu, plo1, 2);
            phi1 += __shfl_xor_sync(0xffffffffu, phi1, 1);
            phi1 += __shfl_xor_sync(0xffffffffu, phi1, 2);
            if (c == 0) {
                rowLO[r0] = rowLO[r0] * f0 + (sc0 ? plo0 : (alllo0 ? ts0 : 0.f));
                rowHI[r0] = rowHI[r0] * f0 + (sc0 ? phi0 : (allhi0 ? ts0 : 0.f));
                rowLO[r1] = rowLO[r1] * f1 + (sc1 ? plo1 : (alllo1 ? ts1 : 0.f));
                rowHI[r1] = rowHI[r1] * f1 + (sc1 ? phi1 : (allhi1 ? ts1 : 0.f));
            }
        }

        // ---- O += P @ V ----
#pragma unroll
        for (int kc2 = 0; kc2 < 128; kc2 += 32) {
            __syncthreads();
            {
                int vrow = tid >> 3, vcol = (tid & 7) * 8;
                float4 v0 = *(const float4*)&Vb[(size_t)(bn + kc2 + vrow) * DKK + vcol];
                float4 v1 = *(const float4*)&Vb[(size_t)(bn + kc2 + vrow) * DKK + vcol + 4];
                v0.x = f2tf(v0.x); v0.y = f2tf(v0.y); v0.z = f2tf(v0.z); v0.w = f2tf(v0.w);
                v1.x = f2tf(v1.x); v1.y = f2tf(v1.y); v1.z = f2tf(v1.z); v1.w = f2tf(v1.w);
                *(float4*)&Vs[vrow * 72 + vcol]     = v0;
                *(float4*)&Vs[vrow * 72 + vcol + 4] = v1;
            }
            __syncthreads();
#pragma unroll
            for (int kk = 0; kk < 4; kk++) {
                int kb = kc2 + kk * 8;
                uint32_t a0 = __float_as_uint(Ps[r0 * 132 + kb + c]);
                uint32_t a1 = __float_as_uint(Ps[r1 * 132 + kb + c]);
                uint32_t a2 = __float_as_uint(Ps[r0 * 132 + kb + c + 4]);
                uint32_t a3 = __float_as_uint(Ps[r1 * 132 + kb + c + 4]);
#pragma unroll
                for (int nt = 0; nt < 8; nt++) {
                    uint32_t b0 = __float_as_uint(Vs[(kk * 8 + c) * 72 + nt * 8 + g]);
                    uint32_t b1 = __float_as_uint(Vs[(kk * 8 + c + 4) * 72 + nt * 8 + g]);
                    mma_tf32(oacc[nt], a0, a1, a2, a3, b0, b1);
                }
            }
        }
        __syncthreads();
    }

    // =============== final epilogue ===============
    if (c == 0) { rowM[r0] = m0; rowM[r1] = m1; }
    __syncthreads();

    // middle-bucket scores -> probabilities (numerators in m_final frame)
    for (int i = tid; i < 128 * 64; i += 256) {
        int row = i >> 6;
        PrS[i] = ex2(PrS[i] - rowM[row]);
    }
    // emb_S into Ps region
    {
        float* Es = Ps;   // [65][68]
        for (int i = tid; i < NREL * 64; i += 256) {
            int r = i >> 6, d = i & 63;
            Es[r * 68 + d] = embS[i];
        }
    }
    __syncthreads();

    // relative-value term: lo/hi + middles
    {
        float* Es = Ps;
        float lo0 = rowLO[r0], hi0 = rowHI[r0];
        float lo1 = rowLO[r1], hi1 = rowHI[r1];
#pragma unroll
        for (int nt = 0; nt < 8; nt++) {
            int dcol = nt * 8 + 2 * c;
            float ea0 = Es[0 * 68 + dcol],  ea1 = Es[0 * 68 + dcol + 1];
            float eb0 = Es[64 * 68 + dcol], eb1 = Es[64 * 68 + dcol + 1];
            oacc[nt][0] += lo0 * ea0 + hi0 * eb0;
            oacc[nt][1] += lo0 * ea1 + hi0 * eb1;
            oacc[nt][2] += lo1 * ea0 + hi1 * eb0;
            oacc[nt][3] += lo1 * ea1 + hi1 * eb1;
        }
        for (int r = 1; r < 64; r++) {
            float p0 = PrS[r0 * 64 + r];
            float p1 = PrS[r1 * 64 + r];
#pragma unroll
            for (int nt = 0; nt < 8; nt++) {
                float e0 = Es[r * 68 + nt * 8 + 2 * c];
                float e1 = Es[r * 68 + nt * 8 + 2 * c + 1];
                oacc[nt][0] += p0 * e0;  oacc[nt][1] += p0 * e1;
                oacc[nt][2] += p1 * e0;  oacc[nt][3] += p1 * e1;
            }
        }
    }

    const float inv0 = 1.f / l0, inv1 = 1.f / l1;
    const int b = bh >> 4, h = bh & 15;
    float* Hp = g_heads + (size_t)b * TT * DM + h * DKK;
#pragma unroll
    for (int nt = 0; nt < 8; nt++) {
        *(float2*)&Hp[(size_t)(bm + r0) * DM + nt * 8 + 2 * c] =
            make_float2(f2tf(oacc[nt][0] * inv0), f2tf(oacc[nt][1] * inv0));
        *(float2*)&Hp[(size_t)(bm + r1) * DM + nt * 8 + 2 * c] =
            make_float2(f2tf(oacc[nt][2] * inv1), f2tf(oacc[nt][3] * inv1));
    }
}

// ---------------------------------------------------------------------------
extern "C" void kernel_launch(void* const* d_in, const int* in_sizes, int n_in,
                              void* d_out, int out_size)
{
    const float* q  = (const float*)d_in[0];
    const float* v  = (const float*)d_in[1];
    const float* WQ = (const float*)d_in[2];
    const float* WK = (const float*)d_in[3];
    const float* WV = (const float*)d_in[4];
    const float* WO = (const float*)d_in[5];
    const float* eQ = (const float*)d_in[6];
    const float* eS = (const float*)d_in[7];
    float* out = (float*)d_out;

    cudaFuncSetAttribute(attn_fused, cudaFuncAttributeMaxDynamicSharedMemorySize,
                         ATTN_SMEM_BYTES);
    cudaFuncSetAttribute(gemm_simt, cudaFuncAttributeMaxDynamicSharedMemorySize,
                         GS_SMEM);

    prep_round<<<4096, 256>>>(q, v);
    prep_transpose<<<dim3(32, 32, 4), 256>>>(WQ, WK, WV, WO);
    gemm_simt<<<dim3(4, 32, 3), 256, GS_SMEM>>>(nullptr, 1);   // Q,K,V projections
    attn_fused<<<dim3(8, BH), 256, ATTN_SMEM_BYTES>>>(eQ, eS);
    gemm_simt<<<dim3(4, 32, 1), 256, GS_SMEM>>>(out, 0);       // output projection
}

// round 16
// speedup vs baseline: 3.4064x; 1.1456x over previous
#include <cuda_runtime.h>
#include <math.h>
#include <stdint.h>

#define TT    1024
#define BB    4
#define HH    16
#define DKK   64
#define DM    1024
#define BH    (BB*HH)      // 64
#define NROWS (BB*TT)      // 4096
#define NREL  65

// ---------------- scratch (device globals; no allocation allowed) ----------
__device__ float g_qW[BH * TT * DKK];            // 16 MB (tf32-rounded)
__device__ float g_kW[BH * TT * DKK];            // 16 MB (tf32-rounded)
__device__ float g_vW[BH * TT * DKK];            // 16 MB (tf32-rounded)
__device__ float g_heads[NROWS * DM];            // 16 MB (tf32-rounded)
__device__ float g_arena[12 * 1024 * 1024];      // 48 MB: Xq, Xv, Bt[4]

#define XQ_OFF   0
#define XV_OFF   (4*1024*1024)
#define BT_OFF   (8*1024*1024)      // + z * 1M floats, z = Q,K,V,O

// ---------------------------------------------------------------------------
// helpers
// ---------------------------------------------------------------------------
__device__ __forceinline__ float f2tf(float x) {
    uint32_t u;
    asm("cvt.rna.tf32.f32 %0, %1;" : "=r"(u) : "f"(x));
    return __uint_as_float(u);
}

__device__ __forceinline__ float ex2(float x) {
    float y;
    asm("ex2.approx.f32 %0, %1;" : "=f"(y) : "f"(x));
    return y;
}

__device__ __forceinline__ void mma_tf32(float c[4],
                                         uint32_t a0, uint32_t a1, uint32_t a2, uint32_t a3,
                                         uint32_t b0, uint32_t b1)
{
    asm volatile(
        "mma.sync.aligned.m16n8k8.row.col.f32.tf32.tf32.f32 "
        "{%0,%1,%2,%3}, {%4,%5,%6,%7}, {%8,%9}, {%0,%1,%2,%3};"
        : "+f"(c[0]), "+f"(c[1]), "+f"(c[2]), "+f"(c[3])
        : "r"(a0), "r"(a1), "r"(a2), "r"(a3), "r"(b0), "r"(b1));
}

__device__ __forceinline__ uint32_t smem_u32(const void* p) {
    return (uint32_t)__cvta_generic_to_shared(p);
}

#define CP16(DST, SRC) \
    asm volatile("cp.async.cg.shared.global [%0], [%1], 16;" \
                 :: "r"(DST), "l"(SRC))
#define CP_COMMIT() asm volatile("cp.async.commit_group;")
#define CP_WAIT0()  asm volatile("cp.async.wait_group 0;")

// ===========================================================================
// prep: round q, v into arena (tf32)
// ===========================================================================
__global__ __launch_bounds__(256) void prep_round(const float* __restrict__ q,
                                                  const float* __restrict__ v)
{
    size_t i = ((size_t)blockIdx.x * 256 + threadIdx.x) * 4;
    float4 a = *(const float4*)&q[i];
    a.x = f2tf(a.x); a.y = f2tf(a.y); a.z = f2tf(a.z); a.w = f2tf(a.w);
    *(float4*)&g_arena[XQ_OFF + i] = a;
    float4 b = *(const float4*)&v[i];
    b.x = f2tf(b.x); b.y = f2tf(b.y); b.z = f2tf(b.z); b.w = f2tf(b.w);
    *(float4*)&g_arena[XV_OFF + i] = b;
}

// ===========================================================================
// prep: transpose + round weights into Bt[n][k] (1024x1024 each)
// ===========================================================================
__global__ __launch_bounds__(256) void prep_transpose(const float* __restrict__ WQ,
                                                      const float* __restrict__ WK,
                                                      const float* __restrict__ WV,
                                                      const float* __restrict__ WO)
{
    __shared__ float tile[32][33];
    const int z = blockIdx.z;
    const float* src = (z == 0) ? WQ : (z == 1) ? WK : (z == 2) ? WV : WO;
    float* dst = g_arena + BT_OFF + (size_t)z * 1024 * 1024;
    const int k0 = blockIdx.x * 32, n0 = blockIdx.y * 32;
    const int tx = threadIdx.x & 31, ty = threadIdx.x >> 5;

#pragma unroll
    for (int i = 0; i < 32; i += 8) {
        int k = k0 + ty + i, n = n0 + tx;
        float val;
        if (z < 3) val = src[(size_t)(n >> 6) * 65536 + (size_t)k * 64 + (n & 63)];
        else       val = src[(size_t)k * 1024 + n];
        tile[ty + i][tx] = f2tf(val);
    }
    __syncthreads();
#pragma unroll
    for (int i = 0; i < 32; i += 8) {
        int n = n0 + ty + i, k = k0 + tx;
        dst[(size_t)n * 1024 + k] = tile[tx][ty + i];
    }
}

// ===========================================================================
// Dense GEMM (mma.sync tf32, pre-rounded operands, cp.async staging).
// mode 1 epilogue stores tf32-rounded outputs (consumed by attn via cp.async).
// ===========================================================================
#define RST  36
#define GA_ROWS 128
#define GB_ROWS 256
#define BUF_FLOATS ((GA_ROWS + GB_ROWS) * RST)
#define GS_SMEM (2 * BUF_FLOATS * 4)

__global__ __launch_bounds__(256) void gemm_simt(float* __restrict__ Cout, int mode)
{
    extern __shared__ float sh[];
    const int tid = threadIdx.x;
    const int z = blockIdx.z;

    const float *A, *B;
    if (mode) {
        A = g_arena + ((z == 0) ? XQ_OFF : XV_OFF);
        B = g_arena + BT_OFF + (size_t)z * 1024 * 1024;
    } else {
        A = g_heads;
        B = g_arena + BT_OFF + (size_t)3 * 1024 * 1024;
    }

    const int bm = blockIdx.y * 128;
    const int bn = blockIdx.x * 256;

    float* bufA[2] = { sh, sh + BUF_FLOATS };
    float* bufB[2] = { sh + GA_ROWS * RST, sh + BUF_FLOATS + GA_ROWS * RST };
    const uint32_t sA[2] = { smem_u32(bufA[0]), smem_u32(bufA[1]) };
    const uint32_t sB[2] = { smem_u32(bufB[0]), smem_u32(bufB[1]) };

    const int warp = tid >> 5, lane = tid & 31;
    const int g = lane >> 2, c = lane & 3;
    const int wm = (warp >> 2) * 64;
    const int wn = (warp & 3) * 64;

    float acc[4][8][4];
#pragma unroll
    for (int i = 0; i < 4; i++)
#pragma unroll
        for (int j = 0; j < 8; j++)
#pragma unroll
            for (int e = 0; e < 4; e++) acc[i][j][e] = 0.f;

#define GS_LOAD(CH, BUF)                                                       \
    {                                                                          \
        const int k0 = (CH) * 32;                                              \
        _Pragma("unroll")                                                      \
        for (int i = 0; i < 4; i++) {                                          \
            int idx = tid + i * 256;                                           \
            int row = idx >> 3, seg = idx & 7;                                 \
            const float* src = A + (size_t)(bm + row) * 1024 + k0 + seg * 4;   \
            CP16(sA[BUF] + (uint32_t)(row * 144 + seg * 16), src);             \
        }                                                                      \
        _Pragma("unroll")                                                      \
        for (int i = 0; i < 8; i++) {                                          \
            int idx = tid + i * 256;                                           \
            int row = idx >> 3, seg = idx & 7;                                 \
            const float* src = B + (size_t)(bn + row) * 1024 + k0 + seg * 4;   \
            CP16(sB[BUF] + (uint32_t)(row * 144 + seg * 16), src);             \
        }                                                                      \
        CP_COMMIT();                                                           \
    }

#define GS_COMPUTE(BUF)                                                        \
    {                                                                          \
        const float* As_ = bufA[BUF];                                          \
        const float* Bs_ = bufB[BUF];                                          \
        _Pragma("unroll")                                                      \
        for (int kk = 0; kk < 4; kk++) {                                       \
            const int kbs = kk * 8;                                            \
            uint32_t af[4][4], bf[8][2];                                       \
            _Pragma("unroll")                                                  \
            for (int mt = 0; mt < 4; mt++) {                                   \
                const int rm = wm + mt * 16;                                   \
                af[mt][0] = __float_as_uint(As_[(rm + g    ) * RST + kbs + c    ]); \
                af[mt][1] = __float_as_uint(As_[(rm + g + 8) * RST + kbs + c    ]); \
                af[mt][2] = __float_as_uint(As_[(rm + g    ) * RST + kbs + c + 4]); \
                af[mt][3] = __float_as_uint(As_[(rm + g + 8) * RST + kbs + c + 4]); \
            }                                                                  \
            _Pragma("unroll")                                                  \
            for (int nt = 0; nt < 8; nt++) {                                   \
                bf[nt][0] = __float_as_uint(Bs_[(wn + nt * 8 + g) * RST + kbs + c    ]); \
                bf[nt][1] = __float_as_uint(Bs_[(wn + nt * 8 + g) * RST + kbs + c + 4]); \
            }                                                                  \
            _Pragma("unroll")                                                  \
            for (int mt = 0; mt < 4; mt++)                                     \
                _Pragma("unroll")                                              \
                for (int nt = 0; nt < 8; nt++)                                 \
                    mma_tf32(acc[mt][nt], af[mt][0], af[mt][1], af[mt][2],     \
                             af[mt][3], bf[nt][0], bf[nt][1]);                 \
        }                                                                      \
    }

    GS_LOAD(0, 0);
    GS_LOAD(1, 1);

    for (int ch = 0; ch < 32; ch++) {
        const int buf = ch & 1;
        if (ch < 31) asm volatile("cp.async.wait_group 1;");
        else         asm volatile("cp.async.wait_group 0;");
        __syncthreads();
        GS_COMPUTE(buf);
        __syncthreads();
        if (ch + 2 < 32) GS_LOAD(ch + 2, buf);
    }

    if (mode == 0) {
#pragma unroll
        for (int mt = 0; mt < 4; mt++) {
            int r = bm + wm + mt * 16 + g;
#pragma unroll
            for (int nt = 0; nt < 8; nt++) {
                int n0 = bn + wn + nt * 8 + 2 * c;
                *(float2*)&Cout[(size_t)r * DM + n0] =
                    make_float2(acc[mt][nt][0], acc[mt][nt][1]);
                *(float2*)&Cout[(size_t)(r + 8) * DM + n0] =
                    make_float2(acc[mt][nt][2], acc[mt][nt][3]);
            }
        }
    } else {
        float* O = (z == 0) ? g_qW : (z == 1) ? g_kW : g_vW;
        const int h = (bn + wn) >> 6;
#pragma unroll
        for (int mt = 0; mt < 4; mt++) {
            int r = bm + wm + mt * 16 + g;
            int b = r >> 10, t = r & 1023;
            size_t base0 = ((size_t)(b * HH + h) * TT + t) * DKK;
            size_t base1 = ((size_t)(b * HH + h) * TT + ((r + 8) & 1023)) * DKK
                         + ((size_t)((r + 8) >> 10) - b) * HH * TT * DKK;
#pragma unroll
            for (int nt = 0; nt < 8; nt++) {
                int d = nt * 8 + 2 * c;
                *(float2*)&O[base0 + d] =
                    make_float2(f2tf(acc[mt][nt][0]), f2tf(acc[mt][nt][1]));
                *(float2*)&O[base1 + d] =
                    make_float2(f2tf(acc[mt][nt][2]), f2tf(acc[mt][nt][3]));
            }
        }
    }
}

// ===========================================================================
// Fused flash attention. All q/k/v pre-rounded tf32 -> cp.async staging,
// no transposes (K row-major [s][k] str 36; V row-major [s][d] str 72),
// double-buffered K/V chunks overlapped with MMA. 7 barriers/tile.
// ===========================================================================
#define SM_AS   0                    // As[128][68]
#define SM_KSA  8704                 // KsA[128][36]
#define SM_KSB  13312                // KsB[128][36]
#define SM_VSA  17920                // VsA[32][72]
#define SM_VSB  20224                // VsB[32][72]
#define SM_RS   22528                // RS[128][66]
#define SM_PR   30976                // PrS[128][64]
#define SM_LO   39168                // rowLO[128]
#define SM_HI   39296                // rowHI[128]
#define SM_M    39424                // rowM[128]
#define SM_E64  39552                // E64[64]
#define SM_PS   39616                // Ps[128][132] (overlays Et / Es)
#define SM_FTOT 56512
#define ATTN_SMEM_BYTES (SM_FTOT * 4)   // 226048 B

__global__ __launch_bounds__(256, 1) void attn_fused(const float* __restrict__ embQ,
                                                     const float* __restrict__ embS)
{
    extern __shared__ float sm[];
    float* As    = sm + SM_AS;    // stride 68
    float* RS    = sm + SM_RS;    // stride 66
    float* PrS   = sm + SM_PR;    // stride 64
    float* rowLO = sm + SM_LO;
    float* rowHI = sm + SM_HI;
    float* rowM  = sm + SM_M;
    float* E64   = sm + SM_E64;
    float* Ps    = sm + SM_PS;    // stride 132
    float* Kbuf[2] = { sm + SM_KSA, sm + SM_KSB };
    float* Vbuf[2] = { sm + SM_VSA, sm + SM_VSB };
    const uint32_t uAS   = smem_u32(As);
    const uint32_t uK[2] = { smem_u32(Kbuf[0]), smem_u32(Kbuf[1]) };
    const uint32_t uV[2] = { smem_u32(Vbuf[0]), smem_u32(Vbuf[1]) };

    const int bh = blockIdx.y;
    const int bm = blockIdx.x * 128;
    const float* Qb = g_qW + (size_t)bh * TT * DKK;
    const float* Kb = g_kW + (size_t)bh * TT * DKK;
    const float* Vb = g_vW + (size_t)bh * TT * DKK;

    const int tid  = threadIdx.x;
    const int warp = tid >> 5, lane = tid & 31;
    const int g = lane >> 2, c = lane & 3;
    const int r0 = warp * 16 + g;
    const int r1 = r0 + 8;

    // K chunk: 128 rows x 32 k -> Ks[128][36]
#define LOAD_K(BN, KC, BUF)                                                    \
    {                                                                          \
        _Pragma("unroll")                                                      \
        for (int i = 0; i < 4; i++) {                                          \
            int idx = tid + i * 256;                                           \
            int row = idx >> 3, seg = idx & 7;                                 \
            CP16(uK[BUF] + (uint32_t)(row * 144 + seg * 16),                   \
                 Kb + (size_t)((BN) + row) * DKK + (KC) + seg * 4);            \
        }                                                                      \
        CP_COMMIT();                                                           \
    }
    // V chunk: 32 rows x 64 d -> Vs[32][72]
#define LOAD_V(BN, VC, BUF)                                                    \
    {                                                                          \
        _Pragma("unroll")                                                      \
        for (int i = 0; i < 2; i++) {                                          \
            int idx = tid + i * 256;                                           \
            int row = idx >> 4, seg = idx & 15;                                \
            CP16(uV[BUF] + (uint32_t)(row * 288 + seg * 16),                   \
                 Vb + (size_t)((BN) + (VC) + row) * DKK + seg * 4);            \
        }                                                                      \
        CP_COMMIT();                                                           \
    }

    // ---------- prologue ----------
    // Q tile via cp.async (pre-rounded)
#pragma unroll
    for (int i = 0; i < 8; i++) {
        int idx = tid + i * 256;
        int row = idx >> 4, seg = idx & 15;
        CP16(uAS + (uint32_t)(row * 272 + seg * 16),
             Qb + (size_t)(bm + row) * DKK + seg * 4);
    }
    CP_COMMIT();
    {
        float* Et = Ps;  // [64][68] transposed emb_Q
        for (int i = tid; i < 4096; i += 256) {
            int k = i & 63, r = i >> 6;
            Et[k * 68 + r] = f2tf(embQ[r * 64 + k]);
        }
        if (tid < 64) E64[tid] = embQ[64 * 64 + tid];
    }
    for (int i = tid; i < 128 * 64; i += 256) PrS[i] = -1e30f;
    if (tid < 128) { rowLO[tid] = 0.f; rowHI[tid] = 0.f; }
    CP_WAIT0();
    __syncthreads();

    // ---------- RS = Q_tile @ emb_Q^T ----------
    {
        float* Et = Ps;
        float racc[8][4];
#pragma unroll
        for (int nt = 0; nt < 8; nt++)
#pragma unroll
            for (int e = 0; e < 4; e++) racc[nt][e] = 0.f;
#pragma unroll
        for (int kk = 0; kk < 8; kk++) {
            uint32_t a0 = __float_as_uint(As[r0 * 68 + kk * 8 + c]);
            uint32_t a1 = __float_as_uint(As[r1 * 68 + kk * 8 + c]);
            uint32_t a2 = __float_as_uint(As[r0 * 68 + kk * 8 + c + 4]);
            uint32_t a3 = __float_as_uint(As[r1 * 68 + kk * 8 + c + 4]);
#pragma unroll
            for (int nt = 0; nt < 8; nt++) {
                uint32_t b0 = __float_as_uint(Et[(kk * 8 + c) * 68 + nt * 8 + g]);
                uint32_t b1 = __float_as_uint(Et[(kk * 8 + c + 4) * 68 + nt * 8 + g]);
                mma_tf32(racc[nt], a0, a1, a2, a3, b0, b1);
            }
        }
#pragma unroll
        for (int nt = 0; nt < 8; nt++) {
            *(float2*)&RS[r0 * 66 + nt * 8 + 2 * c] = make_float2(racc[nt][0], racc[nt][1]);
            *(float2*)&RS[r1 * 66 + nt * 8 + 2 * c] = make_float2(racc[nt][2], racc[nt][3]);
        }
    }
    if (tid < 128) {
        float a = 0.f;
#pragma unroll
        for (int k = 0; k < 64; k++) a += As[tid * 68 + k] * E64[k];
        RS[tid * 66 + 64] = a;
    }

    float m0 = -INFINITY, m1 = -INFINITY, l0 = 0.f, l1 = 0.f;
    float oacc[8][4];
#pragma unroll
    for (int nt = 0; nt < 8; nt++)
#pragma unroll
        for (int e = 0; e < 4; e++) oacc[nt][e] = 0.f;

    const float SCL = 0.125f * 1.4426950408889634f;
    const int t0 = bm + r0, t1 = bm + r1;
    __syncthreads();                 // RS done; Ps region free

    LOAD_K(0, 0, 0);                 // prefetch first K chunk

    // MMA chunk helpers
#define SMMA_CHUNK(KB0, KP)                                                    \
    {                                                                          \
        const float* Kp = (KP);                                                \
        _Pragma("unroll")                                                      \
        for (int kk = 0; kk < 4; kk++) {                                       \
            uint32_t a0 = __float_as_uint(As[r0 * 68 + (KB0) + kk * 8 + c]);   \
            uint32_t a1 = __float_as_uint(As[r1 * 68 + (KB0) + kk * 8 + c]);   \
            uint32_t a2 = __float_as_uint(As[r0 * 68 + (KB0) + kk * 8 + c + 4]); \
            uint32_t a3 = __float_as_uint(As[r1 * 68 + (KB0) + kk * 8 + c + 4]); \
            _Pragma("unroll")                                                  \
            for (int nt = 0; nt < 16; nt++) {                                  \
                uint32_t b0 = __float_as_uint(Kp[(nt * 8 + g) * 36 + kk * 8 + c]); \
                uint32_t b1 = __float_as_uint(Kp[(nt * 8 + g) * 36 + kk * 8 + c + 4]); \
                mma_tf32(sacc[nt], a0, a1, a2, a3, b0, b1);                    \
            }                                                                  \
        }                                                                      \
    }

#define PV_CHUNK(PB, VP)                                                       \
    {                                                                          \
        const float* Vp = (VP);                                                \
        _Pragma("unroll")                                                      \
        for (int kk = 0; kk < 4; kk++) {                                       \
            uint32_t a0 = __float_as_uint(Ps[r0 * 132 + (PB) + kk * 8 + c]);   \
            uint32_t a1 = __float_as_uint(Ps[r1 * 132 + (PB) + kk * 8 + c]);   \
            uint32_t a2 = __float_as_uint(Ps[r0 * 132 + (PB) + kk * 8 + c + 4]); \
            uint32_t a3 = __float_as_uint(Ps[r1 * 132 + (PB) + kk * 8 + c + 4]); \
            _Pragma("unroll")                                                  \
            for (int nt = 0; nt < 8; nt++) {                                   \
                uint32_t b0 = __float_as_uint(Vp[(kk * 8 + c) * 72 + nt * 8 + g]); \
                uint32_t b1 = __float_as_uint(Vp[(kk * 8 + c + 4) * 72 + nt * 8 + g]); \
                mma_tf32(oacc[nt], a0, a1, a2, a3, b0, b1);                    \
            }                                                                  \
        }                                                                      \
    }

    // =============== main loop over key tiles ===============
    for (int it = 0; it < 8; it++) {
        const int bn = it * 128;
        float sacc[16][4];
#pragma unroll
        for (int nt = 0; nt < 16; nt++)
#pragma unroll
            for (int e = 0; e < 4; e++) sacc[nt][e] = 0.f;

        CP_WAIT0(); __syncthreads();         // KsA ready
        LOAD_K(bn, 32, 1);
        SMMA_CHUNK(0, Kbuf[0]);
        CP_WAIT0(); __syncthreads();         // KsB ready
        LOAD_V(bn, 0, 0);
        SMMA_CHUNK(32, Kbuf[1]);

        // ---- bias + scale -> base-2 scores; online softmax ----
        float tm0 = -INFINITY, tm1 = -INFINITY;
#pragma unroll
        for (int nt = 0; nt < 16; nt++) {
            int s0 = bn + nt * 8 + 2 * c;
            int d0 = min(max(s0 - t0, -32), 32) + 32;
            int d1 = min(max(s0 + 1 - t0, -32), 32) + 32;
            int d2 = min(max(s0 - t1, -32), 32) + 32;
            int d3 = min(max(s0 + 1 - t1, -32), 32) + 32;
            sacc[nt][0] = (sacc[nt][0] + RS[r0 * 66 + d0]) * SCL;
            sacc[nt][1] = (sacc[nt][1] + RS[r0 * 66 + d1]) * SCL;
            sacc[nt][2] = (sacc[nt][2] + RS[r1 * 66 + d2]) * SCL;
            sacc[nt][3] = (sacc[nt][3] + RS[r1 * 66 + d3]) * SCL;
            tm0 = fmaxf(tm0, fmaxf(sacc[nt][0], sacc[nt][1]));
            tm1 = fmaxf(tm1, fmaxf(sacc[nt][2], sacc[nt][3]));
        }
        tm0 = fmaxf(tm0, __shfl_xor_sync(0xffffffffu, tm0, 1));
        tm0 = fmaxf(tm0, __shfl_xor_sync(0xffffffffu, tm0, 2));
        tm1 = fmaxf(tm1, __shfl_xor_sync(0xffffffffu, tm1, 1));
        tm1 = fmaxf(tm1, __shfl_xor_sync(0xffffffffu, tm1, 2));
        float nm0 = fmaxf(m0, tm0), nm1 = fmaxf(m1, tm1);
        float f0 = ex2(m0 - nm0), f1 = ex2(m1 - nm1);

        float ts0 = 0.f, ts1 = 0.f;
#pragma unroll
        for (int nt = 0; nt < 16; nt++) {
            float p0 = ex2(sacc[nt][0] - nm0);
            float p1 = ex2(sacc[nt][1] - nm0);
            float p2 = ex2(sacc[nt][2] - nm1);
            float p3 = ex2(sacc[nt][3] - nm1);
            ts0 += p0 + p1; ts1 += p2 + p3;
            *(float2*)&Ps[r0 * 132 + nt * 8 + 2 * c] = make_float2(f2tf(p0), f2tf(p1));
            *(float2*)&Ps[r1 * 132 + nt * 8 + 2 * c] = make_float2(f2tf(p2), f2tf(p3));
        }
        ts0 += __shfl_xor_sync(0xffffffffu, ts0, 1);
        ts0 += __shfl_xor_sync(0xffffffffu, ts0, 2);
        ts1 += __shfl_xor_sync(0xffffffffu, ts1, 1);
        ts1 += __shfl_xor_sync(0xffffffffu, ts1, 2);
        l0 = l0 * f0 + ts0;  l1 = l1 * f1 + ts1;
        m0 = nm0;  m1 = nm1;
#pragma unroll
        for (int nt = 0; nt < 8; nt++) {
            oacc[nt][0] *= f0; oacc[nt][1] *= f0;
            oacc[nt][2] *= f1; oacc[nt][3] *= f1;
        }

        // ---- bucket step ----
        {
            const bool alllo0 = (t0 >= bn + 159), allhi0 = (t0 <= bn - 32);
            const bool alllo1 = (t1 >= bn + 159), allhi1 = (t1 <= bn - 32);
            const bool sc0 = !(alllo0 || allhi0);
            const bool sc1 = !(alllo1 || allhi1);
            float plo0 = 0.f, phi0 = 0.f, plo1 = 0.f, phi1 = 0.f;
            if (sc0) {
#pragma unroll
                for (int nt = 0; nt < 16; nt++)
#pragma unroll
                    for (int e = 0; e < 2; e++) {
                        int d = bn + nt * 8 + 2 * c + e - t0;
                        float s2 = sacc[nt][e];
                        if (d <= -32)      plo0 += ex2(s2 - nm0);
                        else if (d >= 32)  phi0 += ex2(s2 - nm0);
                        else               PrS[r0 * 64 + d + 32] = s2;
                    }
            }
            if (sc1) {
#pragma unroll
                for (int nt = 0; nt < 16; nt++)
#pragma unroll
                    for (int e = 0; e < 2; e++) {
                        int d = bn + nt * 8 + 2 * c + e - t1;
                        float s2 = sacc[nt][e + 2];
                        if (d <= -32)      plo1 += ex2(s2 - nm1);
                        else if (d >= 32)  phi1 += ex2(s2 - nm1);
                        else               PrS[r1 * 64 + d + 32] = s2;
                    }
            }
            plo0 += __shfl_xor_sync(0xffffffffu, plo0, 1);
            plo0 += __shfl_xor_sync(0xffffffffu, plo0, 2);
            phi0 += __shfl_xor_sync(0xffffffffu, phi0, 1);
            phi0 += __shfl_xor_sync(0xffffffffu, phi0, 2);
            plo1 += __shfl_xor_sync(0xffffffffu, plo1, 1);
            plo1 += __shfl_xor_sync(0xffffffffu, plo1, 2);
            phi1 += __shfl_xor_sync(0xffffffffu, phi1, 1);
            phi1 += __shfl_xor_sync(0xffffffffu, phi1, 2);
            if (c == 0) {
                rowLO[r0] = rowLO[r0] * f0 + (sc0 ? plo0 : (alllo0 ? ts0 : 0.f));
                rowHI[r0] = rowHI[r0] * f0 + (sc0 ? phi0 : (allhi0 ? ts0 : 0.f));
                rowLO[r1] = rowLO[r1] * f1 + (sc1 ? plo1 : (alllo1 ? ts1 : 0.f));
                rowHI[r1] = rowHI[r1] * f1 + (sc1 ? phi1 : (allhi1 ? ts1 : 0.f));
            }
        }

        // ---- O += P @ V (4 chunks, double-buffered) ----
        CP_WAIT0(); __syncthreads();         // VsA ready + Ps visible
        LOAD_V(bn, 32, 1);
        PV_CHUNK(0, Vbuf[0]);
        CP_WAIT0(); __syncthreads();         // VsB ready + PV c0 done reading VsA
        LOAD_V(bn, 64, 0);
        PV_CHUNK(32, Vbuf[1]);
        CP_WAIT0(); __syncthreads();
        LOAD_V(bn, 96, 1);
        PV_CHUNK(64, Vbuf[0]);
        CP_WAIT0(); __syncthreads();
        if (it < 7) LOAD_K(bn + 128, 0, 0);  // prefetch next K
        PV_CHUNK(96, Vbuf[1]);
    }
    __syncthreads();

    // =============== final epilogue ===============
    if (c == 0) { rowM[r0] = m0; rowM[r1] = m1; }
    __syncthreads();

    for (int i = tid; i < 128 * 64; i += 256) {
        int row = i >> 6;
        PrS[i] = ex2(PrS[i] - rowM[row]);
    }
    {
        float* Es = Ps;   // [65][68]
        for (int i = tid; i < NREL * 64; i += 256) {
            int r = i >> 6, d = i & 63;
            Es[r * 68 + d] = embS[i];
        }
    }
    __syncthreads();

    {
        float* Es = Ps;
        float lo0 = rowLO[r0], hi0 = rowHI[r0];
        float lo1 = rowLO[r1], hi1 = rowHI[r1];
#pragma unroll
        for (int nt = 0; nt < 8; nt++) {
            int dcol = nt * 8 + 2 * c;
            float ea0 = Es[0 * 68 + dcol],  ea1 = Es[0 * 68 + dcol + 1];
            float eb0 = Es[64 * 68 + dcol], eb1 = Es[64 * 68 + dcol + 1];
            oacc[nt][0] += lo0 * ea0 + hi0 * eb0;
            oacc[nt][1] += lo0 * ea1 + hi0 * eb1;
            oacc[nt][2] += lo1 * ea0 + hi1 * eb0;
            oacc[nt][3] += lo1 * ea1 + hi1 * eb1;
        }
        for (int r = 1; r < 64; r++) {
            float p0 = PrS[r0 * 64 + r];
            float p1 = PrS[r1 * 64 + r];
#pragma unroll
            for (int nt = 0; nt < 8; nt++) {
                float e0 = Es[r * 68 + nt * 8 + 2 * c];
                float e1 = Es[r * 68 + nt * 8 + 2 * c + 1];
                oacc[nt][0] += p0 * e0;  oacc[nt][1] += p0 * e1;
                oacc[nt][2] += p1 * e0;  oacc[nt][3] += p1 * e1;
            }
        }
    }

    const float inv0 = 1.f / l0, inv1 = 1.f / l1;
    const int b = bh >> 4, h = bh & 15;
    float* Hp = g_heads + (size_t)b * TT * DM + h * DKK;
#pragma unroll
    for (int nt = 0; nt < 8; nt++) {
        *(float2*)&Hp[(size_t)(bm + r0) * DM + nt * 8 + 2 * c] =
            make_float2(f2tf(oacc[nt][0] * inv0), f2tf(oacc[nt][1] * inv0));
        *(float2*)&Hp[(size_t)(bm + r1) * DM + nt * 8 + 2 * c] =
            make_float2(f2tf(oacc[nt][2] * inv1), f2tf(oacc[nt][3] * inv1));
    }
}

// ---------------------------------------------------------------------------
extern "C" void kernel_launch(void* const* d_in, const int* in_sizes, int n_in,
                              void* d_out, int out_size)
{
    const float* q  = (const float*)d_in[0];
    const float* v  = (const float*)d_in[1];
    const float* WQ = (const float*)d_in[2];
    const float* WK = (const float*)d_in[3];
    const float* WV = (const float*)d_in[4];
    const float* WO = (const float*)d_in[5];
    const float* eQ = (const float*)d_in[6];
    const float* eS = (const float*)d_in[7];
    float* out = (float*)d_out;

    cudaFuncSetAttribute(attn_fused, cudaFuncAttributeMaxDynamicSharedMemorySize,
                         ATTN_SMEM_BYTES);
    cudaFuncSetAttribute(gemm_simt, cudaFuncAttributeMaxDynamicSharedMemorySize,
                         GS_SMEM);

    prep_round<<<4096, 256>>>(q, v);
    prep_transpose<<<dim3(32, 32, 4), 256>>>(WQ, WK, WV, WO);
    gemm_simt<<<dim3(4, 32, 3), 256, GS_SMEM>>>(nullptr, 1);   // Q,K,V projections
    attn_fused<<<dim3(8, BH), 256, ATTN_SMEM_BYTES>>>(eQ, eS);
    gemm_simt<<<dim3(4, 32, 1), 256, GS_SMEM>>>(out, 0);       // output projection
}

// round 17
// speedup vs baseline: 3.4068x; 1.0001x over previous
#include <cuda_runtime.h>
#include <math.h>
#include <stdint.h>

#define TT    1024
#define BB    4
#define HH    16
#define DKK   64
#define DM    1024
#define BH    (BB*HH)      // 64
#define NROWS (BB*TT)      // 4096
#define NREL  65

// ---------------- scratch (device globals; no allocation allowed) ----------
__device__ float g_qW[BH * TT * DKK];            // 16 MB (tf32-rounded)
__device__ float g_kW[BH * TT * DKK];            // 16 MB (tf32-rounded)
__device__ float g_vW[BH * TT * DKK];            // 16 MB (tf32-rounded)
__device__ float g_heads[NROWS * DM];            // 16 MB (tf32-rounded)
__device__ float g_arena[12 * 1024 * 1024];      // 48 MB: Xq, Xv, Bt[4]

#define XQ_OFF   0
#define XV_OFF   (4*1024*1024)
#define BT_OFF   (8*1024*1024)      // + z * 1M floats, z = Q,K,V,O

// ---------------------------------------------------------------------------
// helpers
// ---------------------------------------------------------------------------
__device__ __forceinline__ float f2tf(float x) {
    uint32_t u;
    asm("cvt.rna.tf32.f32 %0, %1;" : "=r"(u) : "f"(x));
    return __uint_as_float(u);
}

__device__ __forceinline__ float ex2(float x) {
    float y;
    asm("ex2.approx.f32 %0, %1;" : "=f"(y) : "f"(x));
    return y;
}

__device__ __forceinline__ void mma_tf32(float c[4],
                                         uint32_t a0, uint32_t a1, uint32_t a2, uint32_t a3,
                                         uint32_t b0, uint32_t b1)
{
    asm volatile(
        "mma.sync.aligned.m16n8k8.row.col.f32.tf32.tf32.f32 "
        "{%0,%1,%2,%3}, {%4,%5,%6,%7}, {%8,%9}, {%0,%1,%2,%3};"
        : "+f"(c[0]), "+f"(c[1]), "+f"(c[2]), "+f"(c[3])
        : "r"(a0), "r"(a1), "r"(a2), "r"(a3), "r"(b0), "r"(b1));
}

__device__ __forceinline__ uint32_t smem_u32(const void* p) {
    return (uint32_t)__cvta_generic_to_shared(p);
}

#define CP16(DST, SRC) \
    asm volatile("cp.async.cg.shared.global [%0], [%1], 16;" \
                 :: "r"(DST), "l"(SRC))
#define CP_COMMIT() asm volatile("cp.async.commit_group;")
#define CP_WAIT0()  asm volatile("cp.async.wait_group 0;")

// ===========================================================================
// prep: round q, v into arena (tf32)
// ===========================================================================
__global__ __launch_bounds__(256) void prep_round(const float* __restrict__ q,
                                                  const float* __restrict__ v)
{
    size_t i = ((size_t)blockIdx.x * 256 + threadIdx.x) * 4;
    float4 a = *(const float4*)&q[i];
    a.x = f2tf(a.x); a.y = f2tf(a.y); a.z = f2tf(a.z); a.w = f2tf(a.w);
    *(float4*)&g_arena[XQ_OFF + i] = a;
    float4 b = *(const float4*)&v[i];
    b.x = f2tf(b.x); b.y = f2tf(b.y); b.z = f2tf(b.z); b.w = f2tf(b.w);
    *(float4*)&g_arena[XV_OFF + i] = b;
}

// ===========================================================================
// prep: transpose + round weights into Bt[n][k] (1024x1024 each)
// ===========================================================================
__global__ __launch_bounds__(256) void prep_transpose(const float* __restrict__ WQ,
                                                      const float* __restrict__ WK,
                                                      const float* __restrict__ WV,
                                                      const float* __restrict__ WO)
{
    __shared__ float tile[32][33];
    const int z = blockIdx.z;
    const float* src = (z == 0) ? WQ : (z == 1) ? WK : (z == 2) ? WV : WO;
    float* dst = g_arena + BT_OFF + (size_t)z * 1024 * 1024;
    const int k0 = blockIdx.x * 32, n0 = blockIdx.y * 32;
    const int tx = threadIdx.x & 31, ty = threadIdx.x >> 5;

#pragma unroll
    for (int i = 0; i < 32; i += 8) {
        int k = k0 + ty + i, n = n0 + tx;
        float val;
        if (z < 3) val = src[(size_t)(n >> 6) * 65536 + (size_t)k * 64 + (n & 63)];
        else       val = src[(size_t)k * 1024 + n];
        tile[ty + i][tx] = f2tf(val);
    }
    __syncthreads();
#pragma unroll
    for (int i = 0; i < 32; i += 8) {
        int n = n0 + ty + i, k = k0 + tx;
        dst[(size_t)n * 1024 + k] = tile[tx][ty + i];
    }
}

// ===========================================================================
// Dense GEMM (mma.sync tf32, pre-rounded operands, cp.async staging).
// ===========================================================================
#define RST  36
#define GA_ROWS 128
#define GB_ROWS 256
#define BUF_FLOATS ((GA_ROWS + GB_ROWS) * RST)
#define GS_SMEM (2 * BUF_FLOATS * 4)

__global__ __launch_bounds__(256) void gemm_simt(float* __restrict__ Cout, int mode)
{
    extern __shared__ float sh[];
    const int tid = threadIdx.x;
    const int z = blockIdx.z;

    const float *A, *B;
    if (mode) {
        A = g_arena + ((z == 0) ? XQ_OFF : XV_OFF);
        B = g_arena + BT_OFF + (size_t)z * 1024 * 1024;
    } else {
        A = g_heads;
        B = g_arena + BT_OFF + (size_t)3 * 1024 * 1024;
    }

    const int bm = blockIdx.y * 128;
    const int bn = blockIdx.x * 256;

    float* bufA[2] = { sh, sh + BUF_FLOATS };
    float* bufB[2] = { sh + GA_ROWS * RST, sh + BUF_FLOATS + GA_ROWS * RST };
    const uint32_t sA[2] = { smem_u32(bufA[0]), smem_u32(bufA[1]) };
    const uint32_t sB[2] = { smem_u32(bufB[0]), smem_u32(bufB[1]) };

    const int warp = tid >> 5, lane = tid & 31;
    const int g = lane >> 2, c = lane & 3;
    const int wm = (warp >> 2) * 64;
    const int wn = (warp & 3) * 64;

    float acc[4][8][4];
#pragma unroll
    for (int i = 0; i < 4; i++)
#pragma unroll
        for (int j = 0; j < 8; j++)
#pragma unroll
            for (int e = 0; e < 4; e++) acc[i][j][e] = 0.f;

#define GS_LOAD(CH, BUF)                                                       \
    {                                                                          \
        const int k0 = (CH) * 32;                                              \
        _Pragma("unroll")                                                      \
        for (int i = 0; i < 4; i++) {                                          \
            int idx = tid + i * 256;                                           \
            int row = idx >> 3, seg = idx & 7;                                 \
            const float* src = A + (size_t)(bm + row) * 1024 + k0 + seg * 4;   \
            CP16(sA[BUF] + (uint32_t)(row * 144 + seg * 16), src);             \
        }                                                                      \
        _Pragma("unroll")                                                      \
        for (int i = 0; i < 8; i++) {                                          \
            int idx = tid + i * 256;                                           \
            int row = idx >> 3, seg = idx & 7;                                 \
            const float* src = B + (size_t)(bn + row) * 1024 + k0 + seg * 4;   \
            CP16(sB[BUF] + (uint32_t)(row * 144 + seg * 16), src);             \
        }                                                                      \
        CP_COMMIT();                                                           \
    }

#define GS_COMPUTE(BUF)                                                        \
    {                                                                          \
        const float* As_ = bufA[BUF];                                          \
        const float* Bs_ = bufB[BUF];                                          \
        _Pragma("unroll")                                                      \
        for (int kk = 0; kk < 4; kk++) {                                       \
            const int kbs = kk * 8;                                            \
            uint32_t af[4][4], bf[8][2];                                       \
            _Pragma("unroll")                                                  \
            for (int mt = 0; mt < 4; mt++) {                                   \
                const int rm = wm + mt * 16;                                   \
                af[mt][0] = __float_as_uint(As_[(rm + g    ) * RST + kbs + c    ]); \
                af[mt][1] = __float_as_uint(As_[(rm + g + 8) * RST + kbs + c    ]); \
                af[mt][2] = __float_as_uint(As_[(rm + g    ) * RST + kbs + c + 4]); \
                af[mt][3] = __float_as_uint(As_[(rm + g + 8) * RST + kbs + c + 4]); \
            }                                                                  \
            _Pragma("unroll")                                                  \
            for (int nt = 0; nt < 8; nt++) {                                   \
                bf[nt][0] = __float_as_uint(Bs_[(wn + nt * 8 + g) * RST + kbs + c    ]); \
                bf[nt][1] = __float_as_uint(Bs_[(wn + nt * 8 + g) * RST + kbs + c + 4]); \
            }                                                                  \
            _Pragma("unroll")                                                  \
            for (int mt = 0; mt < 4; mt++)                                     \
                _Pragma("unroll")                                              \
                for (int nt = 0; nt < 8; nt++)                                 \
                    mma_tf32(acc[mt][nt], af[mt][0], af[mt][1], af[mt][2],     \
                             af[mt][3], bf[nt][0], bf[nt][1]);                 \
        }                                                                      \
    }

    GS_LOAD(0, 0);
    GS_LOAD(1, 1);

    for (int ch = 0; ch < 32; ch++) {
        const int buf = ch & 1;
        if (ch < 31) asm volatile("cp.async.wait_group 1;");
        else         asm volatile("cp.async.wait_group 0;");
        __syncthreads();
        GS_COMPUTE(buf);
        __syncthreads();
        if (ch + 2 < 32) GS_LOAD(ch + 2, buf);
    }

    if (mode == 0) {
#pragma unroll
        for (int mt = 0; mt < 4; mt++) {
            int r = bm + wm + mt * 16 + g;
#pragma unroll
            for (int nt = 0; nt < 8; nt++) {
                int n0 = bn + wn + nt * 8 + 2 * c;
                *(float2*)&Cout[(size_t)r * DM + n0] =
                    make_float2(acc[mt][nt][0], acc[mt][nt][1]);
                *(float2*)&Cout[(size_t)(r + 8) * DM + n0] =
                    make_float2(acc[mt][nt][2], acc[mt][nt][3]);
            }
        }
    } else {
        float* O = (z == 0) ? g_qW : (z == 1) ? g_kW : g_vW;
        const int h = (bn + wn) >> 6;
#pragma unroll
        for (int mt = 0; mt < 4; mt++) {
            int r = bm + wm + mt * 16 + g;
            int b = r >> 10, t = r & 1023;
            size_t base0 = ((size_t)(b * HH + h) * TT + t) * DKK;
            size_t base1 = ((size_t)(b * HH + h) * TT + ((r + 8) & 1023)) * DKK
                         + ((size_t)((r + 8) >> 10) - b) * HH * TT * DKK;
#pragma unroll
            for (int nt = 0; nt < 8; nt++) {
                int d = nt * 8 + 2 * c;
                *(float2*)&O[base0 + d] =
                    make_float2(f2tf(acc[mt][nt][0]), f2tf(acc[mt][nt][1]));
                *(float2*)&O[base1 + d] =
                    make_float2(f2tf(acc[mt][nt][2]), f2tf(acc[mt][nt][3]));
            }
        }
    }
}

// ===========================================================================
// Fused flash attention, 512 threads / 16 warps per 128-row tile.
// warp = (wr = warp>>1 row-group, ch = warp&1 half):
//   S: warp computes rows wr*16..+15, cols ch*64..+63  (sacc[8][4])
//   PV: warp computes rows wr*16..+15, d cols ch*32..+31 (oacc[4][4], full k)
// Row softmax stats combined across halves via tmH/tsH smem arrays.
// ===========================================================================
#define SM_AS   0                    // As[128][68]
#define SM_KSA  8704                 // KsA[128][36]
#define SM_KSB  13312                // KsB[128][36]
#define SM_VSA  17920                // VsA[32][72]
#define SM_VSB  20224                // VsB[32][72]
#define SM_RS   22528                // RS[128][66]
#define SM_PR   30976                // PrS[128][64]
#define SM_LO   39168                // rowLO[128]
#define SM_HI   39296                // rowHI[128]
#define SM_M    39424                // rowM[128]
#define SM_E64  39552                // E64[64]
#define SM_TMH  39616                // tmH[128][2]
#define SM_TSH  39872                // tsH[128][2]
#define SM_LHL  40128                // LHlo[128][2]
#define SM_LHH  40384                // LHhi[128][2]
#define SM_PS   40640                // Ps[128][132] (overlays Et / Es)
#define SM_FTOT 57536
#define ATTN_SMEM_BYTES (SM_FTOT * 4)   // 230144 B

__global__ __launch_bounds__(512, 1) void attn_fused(const float* __restrict__ embQ,
                                                     const float* __restrict__ embS)
{
    extern __shared__ float sm[];
    float* As    = sm + SM_AS;    // stride 68
    float* RS    = sm + SM_RS;    // stride 66
    float* PrS   = sm + SM_PR;    // stride 64
    float* rowLO = sm + SM_LO;
    float* rowHI = sm + SM_HI;
    float* rowM  = sm + SM_M;
    float* E64   = sm + SM_E64;
    float* tmH   = sm + SM_TMH;
    float* tsH   = sm + SM_TSH;
    float* LHl   = sm + SM_LHL;
    float* LHh   = sm + SM_LHH;
    float* Ps    = sm + SM_PS;    // stride 132
    float* Kbuf[2] = { sm + SM_KSA, sm + SM_KSB };
    float* Vbuf[2] = { sm + SM_VSA, sm + SM_VSB };
    const uint32_t uAS   = smem_u32(As);
    const uint32_t uK[2] = { smem_u32(Kbuf[0]), smem_u32(Kbuf[1]) };
    const uint32_t uV[2] = { smem_u32(Vbuf[0]), smem_u32(Vbuf[1]) };

    const int bh = blockIdx.y;
    const int bm = blockIdx.x * 128;
    const float* Qb = g_qW + (size_t)bh * TT * DKK;
    const float* Kb = g_kW + (size_t)bh * TT * DKK;
    const float* Vb = g_vW + (size_t)bh * TT * DKK;

    const int tid  = threadIdx.x;
    const int warp = tid >> 5, lane = tid & 31;
    const int g = lane >> 2, c = lane & 3;
    const int wr = warp >> 1, ch = warp & 1;
    const int r0 = wr * 16 + g;
    const int r1 = r0 + 8;
    const int co = ch * 64;     // S col base for this warp
    const int wd = ch * 32;     // PV d-col base for this warp

    // K chunk: 128 rows x 32 k -> Ks[128][36], 2 cp.async per thread
#define LOAD_K(BN, KC, BUF)                                                    \
    {                                                                          \
        _Pragma("unroll")                                                      \
        for (int i = 0; i < 2; i++) {                                          \
            int idx = tid + i * 512;                                           \
            int row = idx >> 3, seg = idx & 7;                                 \
            CP16(uK[BUF] + (uint32_t)(row * 144 + seg * 16),                   \
                 Kb + (size_t)((BN) + row) * DKK + (KC) + seg * 4);            \
        }                                                                      \
        CP_COMMIT();                                                           \
    }
    // V chunk: 32 rows x 64 d -> Vs[32][72], 1 cp.async per thread
#define LOAD_V(BN, VC, BUF)                                                    \
    {                                                                          \
        int row = tid >> 4, seg = tid & 15;                                    \
        CP16(uV[BUF] + (uint32_t)(row * 288 + seg * 16),                       \
             Vb + (size_t)((BN) + (VC) + row) * DKK + seg * 4);                \
        CP_COMMIT();                                                           \
    }

    // ---------- prologue ----------
#pragma unroll
    for (int i = 0; i < 4; i++) {
        int idx = tid + i * 512;
        int row = idx >> 4, seg = idx & 15;
        CP16(uAS + (uint32_t)(row * 272 + seg * 16),
             Qb + (size_t)(bm + row) * DKK + seg * 4);
    }
    CP_COMMIT();
    {
        float* Et = Ps;  // [64][68] transposed emb_Q
        for (int i = tid; i < 4096; i += 512) {
            int k = i & 63, r = i >> 6;
            Et[k * 68 + r] = f2tf(embQ[r * 64 + k]);
        }
        if (tid < 64) E64[tid] = embQ[64 * 64 + tid];
    }
    for (int i = tid; i < 128 * 64; i += 512) PrS[i] = -1e30f;
    if (tid < 128) { rowLO[tid] = 0.f; rowHI[tid] = 0.f; }
    CP_WAIT0();
    __syncthreads();

    // ---------- RS = Q_tile @ emb_Q^T (cols split across halves) ----------
    {
        float* Et = Ps;
        float racc[4][4];
#pragma unroll
        for (int nt = 0; nt < 4; nt++)
#pragma unroll
            for (int e = 0; e < 4; e++) racc[nt][e] = 0.f;
#pragma unroll
        for (int kk = 0; kk < 8; kk++) {
            uint32_t a0 = __float_as_uint(As[r0 * 68 + kk * 8 + c]);
            uint32_t a1 = __float_as_uint(As[r1 * 68 + kk * 8 + c]);
            uint32_t a2 = __float_as_uint(As[r0 * 68 + kk * 8 + c + 4]);
            uint32_t a3 = __float_as_uint(As[r1 * 68 + kk * 8 + c + 4]);
#pragma unroll
            for (int nt = 0; nt < 4; nt++) {
                uint32_t b0 = __float_as_uint(Et[(kk * 8 + c) * 68 + ch * 32 + nt * 8 + g]);
                uint32_t b1 = __float_as_uint(Et[(kk * 8 + c + 4) * 68 + ch * 32 + nt * 8 + g]);
                mma_tf32(racc[nt], a0, a1, a2, a3, b0, b1);
            }
        }
#pragma unroll
        for (int nt = 0; nt < 4; nt++) {
            *(float2*)&RS[r0 * 66 + ch * 32 + nt * 8 + 2 * c] =
                make_float2(racc[nt][0], racc[nt][1]);
            *(float2*)&RS[r1 * 66 + ch * 32 + nt * 8 + 2 * c] =
                make_float2(racc[nt][2], racc[nt][3]);
        }
    }
    if (tid < 128) {
        float a = 0.f;
#pragma unroll
        for (int k = 0; k < 64; k++) a += As[tid * 68 + k] * E64[k];
        RS[tid * 66 + 64] = a;
    }

    float m0 = -INFINITY, m1 = -INFINITY, l0 = 0.f, l1 = 0.f;
    float oacc[4][4];
#pragma unroll
    for (int nt = 0; nt < 4; nt++)
#pragma unroll
        for (int e = 0; e < 4; e++) oacc[nt][e] = 0.f;

    const float SCL = 0.125f * 1.4426950408889634f;
    const int t0 = bm + r0, t1 = bm + r1;
    __syncthreads();                 // RS done; Ps region free

    LOAD_K(0, 0, 0);                 // prefetch first K chunk

#define SMMA_CHUNK(KB0, KP)                                                    \
    {                                                                          \
        const float* Kp = (KP);                                                \
        _Pragma("unroll")                                                      \
        for (int kk = 0; kk < 4; kk++) {                                       \
            uint32_t a0 = __float_as_uint(As[r0 * 68 + (KB0) + kk * 8 + c]);   \
            uint32_t a1 = __float_as_uint(As[r1 * 68 + (KB0) + kk * 8 + c]);   \
            uint32_t a2 = __float_as_uint(As[r0 * 68 + (KB0) + kk * 8 + c + 4]); \
            uint32_t a3 = __float_as_uint(As[r1 * 68 + (KB0) + kk * 8 + c + 4]); \
            _Pragma("unroll")                                                  \
            for (int nt = 0; nt < 8; nt++) {                                   \
                uint32_t b0 = __float_as_uint(Kp[(co + nt * 8 + g) * 36 + kk * 8 + c]); \
                uint32_t b1 = __float_as_uint(Kp[(co + nt * 8 + g) * 36 + kk * 8 + c + 4]); \
                mma_tf32(sacc[nt], a0, a1, a2, a3, b0, b1);                    \
            }                                                                  \
        }                                                                      \
    }

#define PV_CHUNK(PB, VP)                                                       \
    {                                                                          \
        const float* Vp = (VP);                                                \
        _Pragma("unroll")                                                      \
        for (int kk = 0; kk < 4; kk++) {                                       \
            uint32_t a0 = __float_as_uint(Ps[r0 * 132 + (PB) + kk * 8 + c]);   \
            uint32_t a1 = __float_as_uint(Ps[r1 * 132 + (PB) + kk * 8 + c]);   \
            uint32_t a2 = __float_as_uint(Ps[r0 * 132 + (PB) + kk * 8 + c + 4]); \
            uint32_t a3 = __float_as_uint(Ps[r1 * 132 + (PB) + kk * 8 + c + 4]); \
            _Pragma("unroll")                                                  \
            for (int nt = 0; nt < 4; nt++) {                                   \
                uint32_t b0 = __float_as_uint(Vp[(kk * 8 + c) * 72 + wd + nt * 8 + g]); \
                uint32_t b1 = __float_as_uint(Vp[(kk * 8 + c + 4) * 72 + wd + nt * 8 + g]); \
                mma_tf32(oacc[nt], a0, a1, a2, a3, b0, b1);                    \
            }                                                                  \
        }                                                                      \
    }

    // =============== main loop over key tiles ===============
    for (int it = 0; it < 8; it++) {
        const int bn = it * 128;
        float sacc[8][4];
#pragma unroll
        for (int nt = 0; nt < 8; nt++)
#pragma unroll
            for (int e = 0; e < 4; e++) sacc[nt][e] = 0.f;

        CP_WAIT0(); __syncthreads();         // KsA ready
        LOAD_K(bn, 32, 1);
        SMMA_CHUNK(0, Kbuf[0]);
        CP_WAIT0(); __syncthreads();         // KsB ready
        LOAD_V(bn, 0, 0);
        SMMA_CHUNK(32, Kbuf[1]);

        // ---- bias + scale -> base-2 scores; local tile max ----
        float tm0 = -INFINITY, tm1 = -INFINITY;
#pragma unroll
        for (int nt = 0; nt < 8; nt++) {
            int s0 = bn + co + nt * 8 + 2 * c;
            int d0 = min(max(s0 - t0, -32), 32) + 32;
            int d1 = min(max(s0 + 1 - t0, -32), 32) + 32;
            int d2 = min(max(s0 - t1, -32), 32) + 32;
            int d3 = min(max(s0 + 1 - t1, -32), 32) + 32;
            sacc[nt][0] = (sacc[nt][0] + RS[r0 * 66 + d0]) * SCL;
            sacc[nt][1] = (sacc[nt][1] + RS[r0 * 66 + d1]) * SCL;
            sacc[nt][2] = (sacc[nt][2] + RS[r1 * 66 + d2]) * SCL;
            sacc[nt][3] = (sacc[nt][3] + RS[r1 * 66 + d3]) * SCL;
            tm0 = fmaxf(tm0, fmaxf(sacc[nt][0], sacc[nt][1]));
            tm1 = fmaxf(tm1, fmaxf(sacc[nt][2], sacc[nt][3]));
        }
        tm0 = fmaxf(tm0, __shfl_xor_sync(0xffffffffu, tm0, 1));
        tm0 = fmaxf(tm0, __shfl_xor_sync(0xffffffffu, tm0, 2));
        tm1 = fmaxf(tm1, __shfl_xor_sync(0xffffffffu, tm1, 1));
        tm1 = fmaxf(tm1, __shfl_xor_sync(0xffffffffu, tm1, 2));
        if (c == 0) { tmH[r0 * 2 + ch] = tm0; tmH[r1 * 2 + ch] = tm1; }
        __syncthreads();                     // (A) tmH visible
        tm0 = fmaxf(tmH[r0 * 2], tmH[r0 * 2 + 1]);
        tm1 = fmaxf(tmH[r1 * 2], tmH[r1 * 2 + 1]);
        float nm0 = fmaxf(m0, tm0), nm1 = fmaxf(m1, tm1);
        float f0 = ex2(m0 - nm0), f1 = ex2(m1 - nm1);

        // ---- probs, Ps stores, local row-sums ----
        float ts0 = 0.f, ts1 = 0.f;
#pragma unroll
        for (int nt = 0; nt < 8; nt++) {
            float p0 = ex2(sacc[nt][0] - nm0);
            float p1 = ex2(sacc[nt][1] - nm0);
            float p2 = ex2(sacc[nt][2] - nm1);
            float p3 = ex2(sacc[nt][3] - nm1);
            ts0 += p0 + p1; ts1 += p2 + p3;
            *(float2*)&Ps[r0 * 132 + co + nt * 8 + 2 * c] = make_float2(f2tf(p0), f2tf(p1));
            *(float2*)&Ps[r1 * 132 + co + nt * 8 + 2 * c] = make_float2(f2tf(p2), f2tf(p3));
        }
        ts0 += __shfl_xor_sync(0xffffffffu, ts0, 1);
        ts0 += __shfl_xor_sync(0xffffffffu, ts0, 2);
        ts1 += __shfl_xor_sync(0xffffffffu, ts1, 1);
        ts1 += __shfl_xor_sync(0xffffffffu, ts1, 2);

        // ---- bucket scan (this warp's cols only) ----
        {
            const bool alllo0 = (t0 >= bn + 159), allhi0 = (t0 <= bn - 32);
            const bool alllo1 = (t1 >= bn + 159), allhi1 = (t1 <= bn - 32);
            const bool sc0 = !(alllo0 || allhi0);
            const bool sc1 = !(alllo1 || allhi1);
            float plo0 = 0.f, phi0 = 0.f, plo1 = 0.f, phi1 = 0.f;
            if (sc0) {
#pragma unroll
                for (int nt = 0; nt < 8; nt++)
#pragma unroll
                    for (int e = 0; e < 2; e++) {
                        int d = bn + co + nt * 8 + 2 * c + e - t0;
                        float s2 = sacc[nt][e];
                        if (d <= -32)      plo0 += ex2(s2 - nm0);
                        else if (d >= 32)  phi0 += ex2(s2 - nm0);
                        else               PrS[r0 * 64 + d + 32] = s2;
                    }
            }
            if (sc1) {
#pragma unroll
                for (int nt = 0; nt < 8; nt++)
#pragma unroll
                    for (int e = 0; e < 2; e++) {
                        int d = bn + co + nt * 8 + 2 * c + e - t1;
                        float s2 = sacc[nt][e + 2];
                        if (d <= -32)      plo1 += ex2(s2 - nm1);
                        else if (d >= 32)  phi1 += ex2(s2 - nm1);
                        else               PrS[r1 * 64 + d + 32] = s2;
                    }
            }
            plo0 += __shfl_xor_sync(0xffffffffu, plo0, 1);
            plo0 += __shfl_xor_sync(0xffffffffu, plo0, 2);
            phi0 += __shfl_xor_sync(0xffffffffu, phi0, 1);
            phi0 += __shfl_xor_sync(0xffffffffu, phi0, 2);
            plo1 += __shfl_xor_sync(0xffffffffu, plo1, 1);
            plo1 += __shfl_xor_sync(0xffffffffu, plo1, 2);
            phi1 += __shfl_xor_sync(0xffffffffu, phi1, 1);
            phi1 += __shfl_xor_sync(0xffffffffu, phi1, 2);
            if (c == 0) {
                tsH[r0 * 2 + ch] = ts0;  tsH[r1 * 2 + ch] = ts1;
                LHl[r0 * 2 + ch] = plo0; LHl[r1 * 2 + ch] = plo1;
                LHh[r0 * 2 + ch] = phi0; LHh[r1 * 2 + ch] = phi1;
            }
        }
        CP_WAIT0();                          // V chunk 0 arrived
        __syncthreads();                     // (B) Ps, tsH, LH visible

        // ---- combine stats; update online state ----
        ts0 = tsH[r0 * 2] + tsH[r0 * 2 + 1];
        ts1 = tsH[r1 * 2] + tsH[r1 * 2 + 1];
        l0 = l0 * f0 + ts0;  l1 = l1 * f1 + ts1;
        m0 = nm0;  m1 = nm1;
#pragma unroll
        for (int nt = 0; nt < 4; nt++) {
            oacc[nt][0] *= f0; oacc[nt][1] *= f0;
            oacc[nt][2] *= f1; oacc[nt][3] *= f1;
        }
        if (ch == 0 && c == 0) {
            const bool alllo0 = (t0 >= bn + 159), allhi0 = (t0 <= bn - 32);
            const bool alllo1 = (t1 >= bn + 159), allhi1 = (t1 <= bn - 32);
            const bool sc0 = !(alllo0 || allhi0);
            const bool sc1 = !(alllo1 || allhi1);
            rowLO[r0] = rowLO[r0] * f0 +
                (sc0 ? (LHl[r0 * 2] + LHl[r0 * 2 + 1]) : (alllo0 ? ts0 : 0.f));
            rowHI[r0] = rowHI[r0] * f0 +
                (sc0 ? (LHh[r0 * 2] + LHh[r0 * 2 + 1]) : (allhi0 ? ts0 : 0.f));
            rowLO[r1] = rowLO[r1] * f1 +
                (sc1 ? (LHl[r1 * 2] + LHl[r1 * 2 + 1]) : (alllo1 ? ts1 : 0.f));
            rowHI[r1] = rowHI[r1] * f1 +
                (sc1 ? (LHh[r1 * 2] + LHh[r1 * 2 + 1]) : (allhi1 ? ts1 : 0.f));
        }

        // ---- O += P @ V (4 chunks, double-buffered) ----
        LOAD_V(bn, 32, 1);
        PV_CHUNK(0, Vbuf[0]);
        CP_WAIT0(); __syncthreads();         // (C)
        LOAD_V(bn, 64, 0);
        PV_CHUNK(32, Vbuf[1]);
        CP_WAIT0(); __syncthreads();         // (D)
        LOAD_V(bn, 96, 1);
        PV_CHUNK(64, Vbuf[0]);
        CP_WAIT0(); __syncthreads();         // (E)
        if (it < 7) LOAD_K(bn + 128, 0, 0);
        PV_CHUNK(96, Vbuf[1]);
    }
    __syncthreads();

    // =============== final epilogue ===============
    if (ch == 0 && c == 0) { rowM[r0] = m0; rowM[r1] = m1; }
    __syncthreads();

    for (int i = tid; i < 128 * 64; i += 512) {
        int row = i >> 6;
        PrS[i] = ex2(PrS[i] - rowM[row]);
    }
    {
        float* Es = Ps;   // [65][68]
        for (int i = tid; i < NREL * 64; i += 512) {
            int r = i >> 6, d = i & 63;
            Es[r * 68 + d] = embS[i];
        }
    }
    __syncthreads();

    {
        float* Es = Ps;
        float lo0 = rowLO[r0], hi0 = rowHI[r0];
        float lo1 = rowLO[r1], hi1 = rowHI[r1];
#pragma unroll
        for (int nt = 0; nt < 4; nt++) {
            int dcol = wd + nt * 8 + 2 * c;
            float ea0 = Es[0 * 68 + dcol],  ea1 = Es[0 * 68 + dcol + 1];
            float eb0 = Es[64 * 68 + dcol], eb1 = Es[64 * 68 + dcol + 1];
            oacc[nt][0] += lo0 * ea0 + hi0 * eb0;
            oacc[nt][1] += lo0 * ea1 + hi0 * eb1;
            oacc[nt][2] += lo1 * ea0 + hi1 * eb0;
            oacc[nt][3] += lo1 * ea1 + hi1 * eb1;
        }
        for (int r = 1; r < 64; r++) {
            float p0 = PrS[r0 * 64 + r];
            float p1 = PrS[r1 * 64 + r];
#pragma unroll
            for (int nt = 0; nt < 4; nt++) {
                float e0 = Es[r * 68 + wd + nt * 8 + 2 * c];
                float e1 = Es[r * 68 + wd + nt * 8 + 2 * c + 1];
                oacc[nt][0] += p0 * e0;  oacc[nt][1] += p0 * e1;
                oacc[nt][2] += p1 * e0;  oacc[nt][3] += p1 * e1;
            }
        }
    }

    const float inv0 = 1.f / l0, inv1 = 1.f / l1;
    const int b = bh >> 4, h = bh & 15;
    float* Hp = g_heads + (size_t)b * TT * DM + h * DKK;
#pragma unroll
    for (int nt = 0; nt < 4; nt++) {
        int dcol = wd + nt * 8 + 2 * c;
        *(float2*)&Hp[(size_t)(bm + r0) * DM + dcol] =
            make_float2(f2tf(oacc[nt][0] * inv0), f2tf(oacc[nt][1] * inv0));
        *(float2*)&Hp[(size_t)(bm + r1) * DM + dcol] =
            make_float2(f2tf(oacc[nt][2] * inv1), f2tf(oacc[nt][3] * inv1));
    }
}

// ---------------------------------------------------------------------------
extern "C" void kernel_launch(void* const* d_in, const int* in_sizes, int n_in,
                              void* d_out, int out_size)
{
    const float* q  = (const float*)d_in[0];
    const float* v  = (const float*)d_in[1];
    const float* WQ = (const float*)d_in[2];
    const float* WK = (const float*)d_in[3];
    const float* WV = (const float*)d_in[4];
    const float* WO = (const float*)d_in[5];
    const float* eQ = (const float*)d_in[6];
    const float* eS = (const float*)d_in[7];
    float* out = (float*)d_out;

    cudaFuncSetAttribute(attn_fused, cudaFuncAttributeMaxDynamicSharedMemorySize,
                         ATTN_SMEM_BYTES);
    cudaFuncSetAttribute(gemm_simt, cudaFuncAttributeMaxDynamicSharedMemorySize,
                         GS_SMEM);

    prep_round<<<4096, 256>>>(q, v);
    prep_transpose<<<dim3(32, 32, 4), 256>>>(WQ, WK, WV, WO);
    gemm_simt<<<dim3(4, 32, 3), 256, GS_SMEM>>>(nullptr, 1);   // Q,K,V projections
    attn_fused<<<dim3(8, BH), 512, ATTN_SMEM_BYTES>>>(eQ, eS);
    gemm_simt<<<dim3(4, 32, 1), 256, GS_SMEM>>>(out, 0);       // output projection
}